// round 12
// baseline (speedup 1.0000x reference)
#include <cuda_runtime.h>
#include <cuda_fp16.h>
#include <math_constants.h>
#include <cstdint>

// ---------------- problem constants ----------------
#define PB 16
#define PN 256
#define PD 1024
#define PH 16
#define PDK 64
#define GM (PB*PN)   // 4096

#define LAM_ATT 0.33f
#define LAM_DIST 0.33f
__device__ __constant__ float LAM_ADJ_C = (float)(1.0 - 0.33 - 0.33);

// ---------------- device scratch ----------------
__device__ float g_pd[PB*PN*PN];

__device__ __half g_w[4][PD*PD];          // weights transposed [n][k], fp16 rounded
__device__ __half g_ah[3][GM*PD];         // activations hi
__device__ __half g_al[3][GM*PD];         // activations lo
// projected tensors, head layout [b][h][n][dk]
__device__ __half g_q2h[GM*PD]; __device__ __half g_q2l[GM*PD];   // Q split
__device__ __half g_k1[GM*PD];                                    // K single
__device__ __half g_v1[GM*PD];                                    // V single
// attention output, split, [m][d]
__device__ __half g_xh[GM*PD]; __device__ __half g_xl[GM*PD];

// ---------------- helpers ----------------
__device__ __forceinline__ uint32_t h2_u32(__half2 v) {
    union { __half2 h; uint32_t u; } c; c.h = v; return c.u;
}
__device__ __forceinline__ uint32_t smem_u32(const void* p) {
    uint32_t a;
    asm("{ .reg .u64 t; cvta.to.shared.u64 t, %1; cvt.u32.u64 %0, t; }" : "=r"(a) : "l"(p));
    return a;
}
__device__ __forceinline__ void cp16(uint32_t dst, const void* src) {
    asm volatile("cp.async.cg.shared.global [%0], [%1], 16;" :: "r"(dst), "l"(src) : "memory");
}
#define CP_COMMIT() asm volatile("cp.async.commit_group;" ::: "memory")
#define CP_WAIT0()  asm volatile("cp.async.wait_group 0;" ::: "memory")
#define CP_WAIT1()  asm volatile("cp.async.wait_group 1;" ::: "memory")

__device__ __forceinline__ void ldm_x4(uint32_t a, uint32_t* r) {
    asm volatile("ldmatrix.sync.aligned.m8n8.x4.shared.b16 {%0,%1,%2,%3}, [%4];"
                 : "=r"(r[0]), "=r"(r[1]), "=r"(r[2]), "=r"(r[3]) : "r"(a));
}
__device__ __forceinline__ void ldm_x2_t(uint32_t a, uint32_t* r) {
    asm volatile("ldmatrix.sync.aligned.m8n8.x2.trans.shared.b16 {%0,%1}, [%2];"
                 : "=r"(r[0]), "=r"(r[1]) : "r"(a));
}
__device__ __forceinline__ void mma16816(float* c, const uint32_t* a, const uint32_t* b) {
    asm volatile("mma.sync.aligned.m16n8k16.row.col.f32.f16.f16.f32 "
                 "{%0,%1,%2,%3}, {%4,%5,%6,%7}, {%8,%9}, {%0,%1,%2,%3};"
                 : "+f"(c[0]), "+f"(c[1]), "+f"(c[2]), "+f"(c[3])
                 : "r"(a[0]), "r"(a[1]), "r"(a[2]), "r"(a[3]), "r"(b[0]), "r"(b[1]));
}
__device__ __forceinline__ void sts32f(uint32_t addr, float v) {
    asm volatile("st.shared.f32 [%0], %1;" :: "r"(addr), "f"(v) : "memory");
}
__device__ __forceinline__ float lds32f(uint32_t addr) {
    float v; asm volatile("ld.shared.f32 %0, [%1];" : "=f"(v) : "r"(addr)); return v;
}
__device__ __forceinline__ float4 lds128f(uint32_t addr) {
    float4 v;
    asm volatile("ld.shared.v4.f32 {%0,%1,%2,%3}, [%4];"
                 : "=f"(v.x), "=f"(v.y), "=f"(v.z), "=f"(v.w) : "r"(addr));
    return v;
}
__device__ __forceinline__ void sts128u(uint32_t addr, uint32_t a, uint32_t b, uint32_t c, uint32_t d) {
    asm volatile("st.shared.v4.b32 [%0], {%1,%2,%3,%4};"
                 :: "r"(addr), "r"(a), "r"(b), "r"(c), "r"(d) : "memory");
}
__device__ __forceinline__ void sts64f(uint32_t addr, float a, float b) {
    asm volatile("st.shared.v2.f32 [%0], {%1,%2};" :: "r"(addr), "f"(a), "f"(b) : "memory");
}

// ---------------------------------------------------------------------------
// prep kernels
// ---------------------------------------------------------------------------
__global__ __launch_bounds__(256)
void wt_kernel(const float* __restrict__ W0, const float* __restrict__ W1,
               const float* __restrict__ W2, const float* __restrict__ W3)
{
    __shared__ float t[32][33];
    const int z = blockIdx.z;
    const float* W = (z == 0) ? W0 : (z == 1) ? W1 : (z == 2) ? W2 : W3;
    __half* O = g_w[z];
    const int n0 = blockIdx.x * 32, k0 = blockIdx.y * 32;
    const int tx = threadIdx.x & 31, ty = threadIdx.x >> 5;
#pragma unroll
    for (int i = 0; i < 4; i++)
        t[ty + i*8][tx] = W[(size_t)(k0 + ty + i*8) * PD + n0 + tx];
    __syncthreads();
#pragma unroll
    for (int i = 0; i < 4; i++) {
        const int n = n0 + ty + i*8;
        O[(size_t)n * PD + k0 + tx] = __float2half_rn(t[tx][ty + i*8]);
    }
}

__device__ __forceinline__ void split_vec(const float* __restrict__ src,
                                          __half* __restrict__ hi,
                                          __half* __restrict__ lo, int i)
{
    const float4 v = ((const float4*)src)[i];
    const __half hx = __float2half_rn(v.x);
    const __half hy = __float2half_rn(v.y);
    const __half hz = __float2half_rn(v.z);
    const __half hw = __float2half_rn(v.w);
    __half2* H = (__half2*)hi;
    __half2* L = (__half2*)lo;
    H[i*2 + 0] = __halves2half2(hx, hy);
    H[i*2 + 1] = __halves2half2(hz, hw);
    L[i*2 + 0] = __halves2half2(__float2half_rn(v.x - __half2float(hx)),
                                __float2half_rn(v.y - __half2float(hy)));
    L[i*2 + 1] = __halves2half2(__float2half_rn(v.z - __half2float(hz)),
                                __float2half_rn(v.w - __half2float(hw)));
}

__global__ __launch_bounds__(256)
void split_qkv_kernel(const float* __restrict__ q, const float* __restrict__ k,
                      const float* __restrict__ v)
{
    const int z = blockIdx.y;
    const float* src = (z == 0) ? q : (z == 1) ? k : v;
    split_vec(src, g_ah[z], g_al[z], blockIdx.x * 256 + threadIdx.x);
}

// ---------------------------------------------------------------------------
// fp16 2-product GEMM: C = (Ah+Al) @ B^T (+bias)
// CTA 128x128, KC=32, 3-stage cp.async; smem/chunk = 24KB (Ah|Al|B)
// out_mode 0: fp32 [m][n] + bias
// out_mode 1: Q split hi/lo to head layout
// out_mode 2: single fp16 to head layout
// ---------------------------------------------------------------------------
#define KCH 32
#define NCHUNK (PD / KCH)
#define VOFF 8192
#define BUFOFF 24576
#define GEMM_DYN (3 * BUFOFF)     // 73728

__device__ __forceinline__ void stage_chunk(
    uint32_t sb, const __half* __restrict__ Ah, const __half* __restrict__ Al,
    const __half* __restrict__ B, int m0, int n0, int kt, int tid)
{
#pragma unroll
    for (int i = 0; i < 2; ++i) {
        const int idx = tid + i * 256;
        const int row = idx >> 2;
        const int seg = idx & 3;
        const uint32_t doff = (uint32_t)(row * 64 + ((seg ^ ((row >> 1) & 3)) * 16));
        const size_t aoff = (size_t)(m0 + row) * PD + kt + seg * 8;
        const size_t boff = (size_t)(n0 + row) * PD + kt + seg * 8;
        cp16(sb + 0*VOFF + doff, Ah + aoff);
        cp16(sb + 1*VOFF + doff, Al + aoff);
        cp16(sb + 2*VOFF + doff, B + boff);
    }
}

__device__ __forceinline__ void gemm_core(
    const __half* __restrict__ Ah, const __half* __restrict__ Al,
    const __half* __restrict__ B, const float* __restrict__ bias,
    float* __restrict__ C, __half* __restrict__ Ch, __half* __restrict__ Cl,
    int out_mode)
{
    extern __shared__ char dsm[];
    const uint32_t sb = smem_u32(dsm);
    const int tid  = threadIdx.x;
    const int wid  = tid >> 5;
    const int lane = tid & 31;
    const int m0 = blockIdx.y * 128;
    const int n0 = blockIdx.x * 128;

    const int wm = (wid & 1) * 64;
    const int wn = (wid >> 1) * 32;

    const int ag   = lane >> 3;
    const int arow = wm + (lane & 7) + 8 * (ag & 1);
    const int aseg = ag >> 1;
    const uint32_t a_off = (uint32_t)(arow * 64 + ((aseg ^ ((arow >> 1) & 3)) * 16));

    const int bsg  = (lane >> 3) & 1;
    const int brow_in = ((lane >> 4) & 1) * 8 + (lane & 7);
    const int brow0 = wn + brow_in;
    const int brow1 = wn + 16 + brow_in;
    const uint32_t b_off0 = (uint32_t)(brow0 * 64 + ((bsg ^ ((brow0 >> 1) & 3)) * 16));
    const uint32_t b_off1 = (uint32_t)(brow1 * 64 + ((bsg ^ ((brow1 >> 1) & 3)) * 16));

    float acc[4][4][4];
#pragma unroll
    for (int mt = 0; mt < 4; mt++)
#pragma unroll
        for (int nt = 0; nt < 4; nt++)
#pragma unroll
            for (int r = 0; r < 4; r++) acc[mt][nt][r] = 0.f;

    stage_chunk(sb + 0*BUFOFF, Ah, Al, B, m0, n0, 0*KCH, tid);
    CP_COMMIT();
    stage_chunk(sb + 1*BUFOFF, Ah, Al, B, m0, n0, 1*KCH, tid);
    CP_COMMIT();

    int bufidx = 0, stageidx = 2;
    for (int c = 0; c < NCHUNK; ++c) {
        if (c + 1 < NCHUNK) { CP_WAIT1(); } else { CP_WAIT0(); }
        __syncthreads();
        if (c + 2 < NCHUNK) {
            stage_chunk(sb + stageidx * BUFOFF, Ah, Al, B, m0, n0, (c + 2) * KCH, tid);
            CP_COMMIT();
            stageidx = (stageidx == 2) ? 0 : stageidx + 1;
        }
        const uint32_t buf = sb + bufidx * BUFOFF;
        bufidx = (bufidx == 2) ? 0 : bufidx + 1;

#pragma unroll
        for (int ks = 0; ks < 2; ++ks) {
            const uint32_t kx = ks * 32;
            uint32_t ah[4][4], al[4][4], bh[4][2];
#pragma unroll
            for (int mt = 0; mt < 4; mt++)
                ldm_x4(buf + 0*VOFF + mt*1024 + (a_off ^ kx), ah[mt]);
            ldm_x4(buf + 2*VOFF + (b_off0 ^ kx), &bh[0][0]);
            ldm_x4(buf + 2*VOFF + (b_off1 ^ kx), &bh[2][0]);
#pragma unroll
            for (int mt = 0; mt < 4; mt++)
#pragma unroll
                for (int nt = 0; nt < 4; nt++)
                    mma16816(acc[mt][nt], ah[mt], bh[nt]);
#pragma unroll
            for (int mt = 0; mt < 4; mt++)
                ldm_x4(buf + 1*VOFF + mt*1024 + (a_off ^ kx), al[mt]);
#pragma unroll
            for (int mt = 0; mt < 4; mt++)
#pragma unroll
                for (int nt = 0; nt < 4; nt++)
                    mma16816(acc[mt][nt], al[mt], bh[nt]);
        }
        // no bottom __syncthreads needed: 3-stage distance + top sync protect buffers
    }

    const int g4 = lane >> 2;
    const int t4 = lane & 3;
#pragma unroll
    for (int nt = 0; nt < 4; nt++) {
        const int col = n0 + wn + nt * 8 + t4 * 2;
        const float2 bv = *(const float2*)(bias + col);
#pragma unroll
        for (int mt = 0; mt < 4; mt++) {
            const int row = m0 + wm + mt * 16 + g4;
            float2 v0, v1;
            v0.x = acc[mt][nt][0] + bv.x;  v0.y = acc[mt][nt][1] + bv.y;
            v1.x = acc[mt][nt][2] + bv.x;  v1.y = acc[mt][nt][3] + bv.y;
            if (out_mode == 0) {
                *(float2*)(C + (size_t)row * PD + col)       = v0;
                *(float2*)(C + (size_t)(row + 8) * PD + col) = v1;
            } else {
                const int b = row >> 8, h = col >> 6, dk = col & 63;
                const int nn = row & 255;
                const size_t base = (((size_t)(b * PH + h)) * PN + nn) * PDK + dk;
                const __half h0x = __float2half_rn(v0.x);
                const __half h0y = __float2half_rn(v0.y);
                const __half h1x = __float2half_rn(v1.x);
                const __half h1y = __float2half_rn(v1.y);
                *(__half2*)(Ch + base)          = __halves2half2(h0x, h0y);
                *(__half2*)(Ch + base + 8*PDK)  = __halves2half2(h1x, h1y);
                if (out_mode == 1) {
                    *(__half2*)(Cl + base) =
                        __halves2half2(__float2half_rn(v0.x - __half2float(h0x)),
                                       __float2half_rn(v0.y - __half2float(h0y)));
                    *(__half2*)(Cl + base + 8*PDK) =
                        __halves2half2(__float2half_rn(v1.x - __half2float(h1x)),
                                       __float2half_rn(v1.y - __half2float(h1y)));
                }
            }
        }
    }
}

__global__ __launch_bounds__(256, 2)
void qkv_mma_kernel(const float* __restrict__ bq, const float* __restrict__ bk,
                    const float* __restrict__ bv)
{
    const int z = blockIdx.z;
    if (z == 0)
        gemm_core(g_ah[0], g_al[0], g_w[0], bq, nullptr, g_q2h, g_q2l, 1);
    else if (z == 1)
        gemm_core(g_ah[1], g_al[1], g_w[1], bk, nullptr, g_k1, nullptr, 2);
    else
        gemm_core(g_ah[2], g_al[2], g_w[2], bv, nullptr, g_v1, nullptr, 2);
}

__global__ __launch_bounds__(256, 2)
void out_mma_kernel(const float* __restrict__ bo, float* __restrict__ out)
{
    gemm_core(g_xh, g_xl, g_w[3], bo, out, nullptr, nullptr, 0);
}

// ---------------------------------------------------------------------------
// pd kernel
// ---------------------------------------------------------------------------
__global__ __launch_bounds__(256)
void pd_kernel(const float* __restrict__ adj, const float* __restrict__ dist,
               const int* __restrict__ mask)
{
    const int bi = blockIdx.x;
    const int b  = bi >> 8;
    const int j  = threadIdx.x;
    const int lane = j & 31, warp = j >> 5;

    const float a  = adj[(size_t)bi*PN + j];
    const int   mj = mask[(b << 8) + j];
    const float nd = mj ? -dist[(size_t)bi*PN + j] : -CUDART_INF_F;

    __shared__ float red[8];

    float v = a;
#pragma unroll
    for (int o = 16; o > 0; o >>= 1) v += __shfl_xor_sync(0xffffffffu, v, o);
    if (lane == 0) red[warp] = v;
    __syncthreads();
    float asum = red[0];
#pragma unroll
    for (int w = 1; w < 8; w++) asum += red[w];
    __syncthreads();

    v = nd;
#pragma unroll
    for (int o = 16; o > 0; o >>= 1) v = fmaxf(v, __shfl_xor_sync(0xffffffffu, v, o));
    if (lane == 0) red[warp] = v;
    __syncthreads();
    float m = red[0];
#pragma unroll
    for (int w = 1; w < 8; w++) m = fmaxf(m, red[w]);
    __syncthreads();

    const float e = mj ? expf(nd - m) : 0.f;
    v = e;
#pragma unroll
    for (int o = 16; o > 0; o >>= 1) v += __shfl_xor_sync(0xffffffffu, v, o);
    if (lane == 0) red[warp] = v;
    __syncthreads();
    float esum = red[0];
#pragma unroll
    for (int w = 1; w < 8; w++) esum += red[w];

    g_pd[(size_t)bi*PN + j] = LAM_ADJ_C * a / (asum + 1e-6f) + LAM_DIST * (e / esum);
}

// ---------------------------------------------------------------------------
// mma attention: one CTA per (b, h, 128-q half)
// smem: Qh|Ql (32KB) | K -> V (32KB) | S/P (130KB) | pen (1KB)  ~195KB
// S row (fp32, 1024B) overwritten in place by P row (fp16, 512B)
// ---------------------------------------------------------------------------
#define SQ_OFF   0
#define SK_OFF   32768
#define SS_OFF   65536
#define SROWB    1040
#define SPEN_OFF (SS_OFF + 128*SROWB)      // 198656
#define ATT_DYN  (SPEN_OFF + 1024)         // 199680

__global__ __launch_bounds__(256, 1)
void attn_mma_kernel(const int* __restrict__ mask)
{
    extern __shared__ char dsm[];
    const uint32_t sb = smem_u32(dsm);
    const int tid = threadIdx.x;
    const int wid = tid >> 5, lane = tid & 31;
    const int b = blockIdx.z, h = blockIdx.y;
    const int q0 = blockIdx.x * 128;
    const int bh = b * PH + h;

    const size_t head = (size_t)bh * PN * PDK;
    const __half* Qh = g_q2h + head + (size_t)q0 * PDK;
    const __half* Ql = g_q2l + head + (size_t)q0 * PDK;

    // stage Q (128x64 hi/lo) and K (256x64), 128B swizzled rows
    for (int i = tid; i < 1024; i += 256) {
        const int row = i >> 3, s = i & 7;
        const uint32_t d = (uint32_t)(row * 128 + ((s ^ (row & 7)) << 4));
        cp16(sb + SQ_OFF + d,         Qh + row * 64 + s * 8);
        cp16(sb + SQ_OFF + 16384 + d, Ql + row * 64 + s * 8);
    }
    for (int i = tid; i < 2048; i += 256) {
        const int row = i >> 3, s = i & 7;
        const uint32_t d = (uint32_t)(row * 128 + ((s ^ (row & 7)) << 4));
        cp16(sb + SK_OFF + d, g_k1 + head + row * 64 + s * 8);
    }
    CP_COMMIT();
    sts32f(sb + SPEN_OFF + tid * 4, mask[(b << 8) + tid] ? 0.f : -1e12f);
    CP_WAIT0();
    __syncthreads();

    // ---------------- phase A: S = (Qh+Ql) @ K^T ----------------
    {
        const int wm = (wid & 1) * 64;
        const int wn = (wid >> 1) * 32;
        const int ag = lane >> 3;
        const int arow = wm + (lane & 7) + 8 * (ag & 1);
        const int aseg0 = ag >> 1;
        const int bsg = (lane >> 3) & 1;
        const int brow_in = ((lane >> 4) & 1) * 8 + (lane & 7);

        for (int nh = 0; nh < 2; ++nh) {
            float acc[4][4][4];
#pragma unroll
            for (int mt = 0; mt < 4; mt++)
#pragma unroll
                for (int nt = 0; nt < 4; nt++)
#pragma unroll
                    for (int r = 0; r < 4; r++) acc[mt][nt][r] = 0.f;

#pragma unroll
            for (int k = 0; k < 4; ++k) {
                uint32_t ahf[4][4], alf[4][4], bhf[4][2];
#pragma unroll
                for (int mt = 0; mt < 4; mt++) {
                    const int r = arow + mt * 16;
                    const uint32_t ad = sb + SQ_OFF + (uint32_t)(r * 128
                                      + (((2*k + aseg0) ^ (r & 7)) << 4));
                    ldm_x4(ad, ahf[mt]);
                    ldm_x4(ad + 16384, alf[mt]);
                }
#pragma unroll
                for (int p = 0; p < 2; p++) {
                    const int r = nh * 128 + wn + p * 16 + brow_in;
                    const uint32_t bd = sb + SK_OFF + (uint32_t)(r * 128
                                      + (((2*k + bsg) ^ (r & 7)) << 4));
                    ldm_x4(bd, &bhf[p*2][0]);
                }
#pragma unroll
                for (int mt = 0; mt < 4; mt++)
#pragma unroll
                    for (int nt = 0; nt < 4; nt++) {
                        mma16816(acc[mt][nt], ahf[mt], bhf[nt]);
                        mma16816(acc[mt][nt], alf[mt], bhf[nt]);
                    }
            }
            const int g4 = lane >> 2, t4 = lane & 3;
#pragma unroll
            for (int mt = 0; mt < 4; mt++) {
                const int row = wm + mt * 16 + g4;
#pragma unroll
                for (int nt = 0; nt < 4; nt++) {
                    const int col = nh * 128 + wn + nt * 8 + t4 * 2;
                    sts64f(sb + SS_OFF + (uint32_t)(row * SROWB + col * 4),
                           acc[mt][nt][0], acc[mt][nt][1]);
                    sts64f(sb + SS_OFF + (uint32_t)((row + 8) * SROWB + col * 4),
                           acc[mt][nt][2], acc[mt][nt][3]);
                }
            }
        }
    }
    __syncthreads();

    // ---------------- phase B: V staging + softmax + pd -> P fp16 (in place)
    for (int i = tid; i < 2048; i += 256) {
        const int row = i >> 3, s = i & 7;
        const uint32_t d = (uint32_t)(row * 128 + ((s ^ (row & 7)) << 4));
        cp16(sb + SK_OFF + d, g_v1 + head + row * 64 + s * 8);
    }
    CP_COMMIT();

    {
        float pen[8];
#pragma unroll
        for (int i = 0; i < 8; i++)
            pen[i] = lds32f(sb + SPEN_OFF + (lane * 8 + i) * 4);
        const float* pdbase = g_pd + ((size_t)b * PN + q0) * PN;

        for (int r = wid * 16; r < wid * 16 + 16; ++r) {
            const uint32_t rb = sb + SS_OFF + (uint32_t)(r * SROWB) + lane * 32;
            float4 s0 = lds128f(rb);
            float4 s1 = lds128f(rb + 16);
            float v[8];
            v[0] = s0.x*0.125f + pen[0]; v[1] = s0.y*0.125f + pen[1];
            v[2] = s0.z*0.125f + pen[2]; v[3] = s0.w*0.125f + pen[3];
            v[4] = s1.x*0.125f + pen[4]; v[5] = s1.y*0.125f + pen[5];
            v[6] = s1.z*0.125f + pen[6]; v[7] = s1.w*0.125f + pen[7];
            float m = v[0];
#pragma unroll
            for (int i = 1; i < 8; i++) m = fmaxf(m, v[i]);
#pragma unroll
            for (int o = 16; o > 0; o >>= 1) m = fmaxf(m, __shfl_xor_sync(0xffffffffu, m, o));
            float e[8], sum = 0.f;
#pragma unroll
            for (int i = 0; i < 8; i++) { e[i] = __expf(v[i] - m); sum += e[i]; }
#pragma unroll
            for (int o = 16; o > 0; o >>= 1) sum += __shfl_xor_sync(0xffffffffu, sum, o);
            const float scale = LAM_ATT / sum;
            const float4 p0 = *(const float4*)(pdbase + (size_t)r * PN + lane * 8);
            const float4 p1 = *(const float4*)(pdbase + (size_t)r * PN + lane * 8 + 4);
            float p[8];
            p[0] = e[0]*scale + p0.x; p[1] = e[1]*scale + p0.y;
            p[2] = e[2]*scale + p0.z; p[3] = e[3]*scale + p0.w;
            p[4] = e[4]*scale + p1.x; p[5] = e[5]*scale + p1.y;
            p[6] = e[6]*scale + p1.z; p[7] = e[7]*scale + p1.w;
            uint32_t hi[4];
#pragma unroll
            for (int i = 0; i < 4; i++)
                hi[i] = h2_u32(__halves2half2(__float2half_rn(p[2*i]),
                                              __float2half_rn(p[2*i+1])));
            const uint32_t pb = sb + SS_OFF + (uint32_t)(r * SROWB) + lane * 16;
            sts128u(pb, hi[0], hi[1], hi[2], hi[3]);
        }
    }
    CP_WAIT0();
    __syncthreads();

    // ---------------- phase C: O = P @ V ----------------
    {
        const int wm = (wid & 1) * 64;
        const int wn = (wid >> 1) * 16;
        const int ag = lane >> 3;
        const int arow = wm + (lane & 7) + 8 * (ag & 1);
        const int aseg0 = ag >> 1;

        float acc[4][2][4];
#pragma unroll
        for (int mt = 0; mt < 4; mt++)
#pragma unroll
            for (int nt = 0; nt < 2; nt++)
#pragma unroll
                for (int r = 0; r < 4; r++) acc[mt][nt][r] = 0.f;

        for (int k = 0; k < 16; ++k) {
            uint32_t ph[4][4], vh[2][2];
#pragma unroll
            for (int mt = 0; mt < 4; mt++) {
                const int r = arow + mt * 16;
                ldm_x4(sb + SS_OFF + (uint32_t)(r * SROWB + (2*k + aseg0) * 16), ph[mt]);
            }
#pragma unroll
            for (int nt = 0; nt < 2; nt++) {
                const int key = k * 16 + (lane & 15);
                const int ds  = (wn >> 3) + nt;
                ldm_x2_t(sb + SK_OFF + (uint32_t)(key * 128 + ((ds ^ (key & 7)) << 4)),
                         vh[nt]);
            }
#pragma unroll
            for (int mt = 0; mt < 4; mt++)
#pragma unroll
                for (int nt = 0; nt < 2; nt++)
                    mma16816(acc[mt][nt], ph[mt], vh[nt]);
        }

        // epilogue: split fp32 O -> g_xh/g_xl at [b*256+q][h*64+dk]
        const int g4 = lane >> 2, t4 = lane & 3;
#pragma unroll
        for (int mt = 0; mt < 4; mt++) {
#pragma unroll
            for (int nt = 0; nt < 2; nt++) {
                const int colg = h * PDK + wn + nt * 8 + t4 * 2;
#pragma unroll
                for (int half = 0; half < 2; half++) {
                    const int mg = b * PN + q0 + wm + mt * 16 + g4 + half * 8;
                    const float vx = acc[mt][nt][half*2 + 0];
                    const float vy = acc[mt][nt][half*2 + 1];
                    const __half hx = __float2half_rn(vx);
                    const __half hy = __float2half_rn(vy);
                    *(__half2*)(g_xh + (size_t)mg * PD + colg) = __halves2half2(hx, hy);
                    *(__half2*)(g_xl + (size_t)mg * PD + colg) =
                        __halves2half2(__float2half_rn(vx - __half2float(hx)),
                                       __float2half_rn(vy - __half2float(hy)));
                }
            }
        }
    }
}

// ---------------------------------------------------------------------------
extern "C" void kernel_launch(void* const* d_in, const int* in_sizes, int n_in,
                              void* d_out, int out_size)
{
    const float* query = (const float*)d_in[0];
    const float* key   = (const float*)d_in[1];
    const float* value = (const float*)d_in[2];
    const float* adj   = (const float*)d_in[3];
    const float* dist  = (const float*)d_in[4];
    const int*   mask  = (const int*)d_in[6];
    const float* Wq = (const float*)d_in[7];
    const float* bq = (const float*)d_in[8];
    const float* Wk = (const float*)d_in[9];
    const float* bk = (const float*)d_in[10];
    const float* Wv = (const float*)d_in[11];
    const float* bv = (const float*)d_in[12];
    const float* Wo = (const float*)d_in[13];
    const float* bo = (const float*)d_in[14];
    float* out = (float*)d_out;

    static bool attr_set = false;
    if (!attr_set) {
        cudaFuncSetAttribute(qkv_mma_kernel, cudaFuncAttributeMaxDynamicSharedMemorySize, GEMM_DYN);
        cudaFuncSetAttribute(out_mma_kernel, cudaFuncAttributeMaxDynamicSharedMemorySize, GEMM_DYN);
        cudaFuncSetAttribute(attn_mma_kernel, cudaFuncAttributeMaxDynamicSharedMemorySize, ATT_DYN);
        attr_set = true;
    }

    wt_kernel<<<dim3(32, 32, 4), 256>>>(Wq, Wk, Wv, Wo);
    split_qkv_kernel<<<dim3(GM*PD/4/256, 3), 256>>>(query, key, value);

    qkv_mma_kernel<<<dim3(PD/128, GM/128, 3), 256, GEMM_DYN>>>(bq, bk, bv);

    pd_kernel<<<PB*PN, 256>>>(adj, dist, mask);

    attn_mma_kernel<<<dim3(2, PH, PB), 256, ATT_DYN>>>(mask);

    out_mma_kernel<<<dim3(PD/128, GM/128, 1), 256, GEMM_DYN>>>(bo, out);
}

// round 13
// speedup vs baseline: 1.4855x; 1.4855x over previous
#include <cuda_runtime.h>
#include <cuda_fp16.h>
#include <math_constants.h>
#include <cstdint>

// ---------------- problem constants ----------------
#define PB 16
#define PN 256
#define PD 1024
#define PH 16
#define PDK 64
#define GM (PB*PN)   // 4096

#define LAM_ATT 0.33f
#define LAM_DIST 0.33f
__device__ __constant__ float LAM_ADJ_C = (float)(1.0 - 0.33 - 0.33);

// ---------------- device scratch ----------------
__device__ float g_pd[PB*PN*PN];

__device__ __half g_w[4][PD*PD];          // weights transposed [n][k], fp16 rounded
__device__ __half g_ah[3][GM*PD];         // activations hi
__device__ __half g_al[3][GM*PD];         // activations lo
// projected tensors, head layout [b][h][n][dk]
__device__ __half g_q2h[GM*PD]; __device__ __half g_q2l[GM*PD];   // Q split
__device__ __half g_k1[GM*PD];                                    // K single
__device__ __half g_v1[GM*PD];                                    // V single
// attention output, split, [m][d]
__device__ __half g_xh[GM*PD]; __device__ __half g_xl[GM*PD];

// ---------------- helpers ----------------
__device__ __forceinline__ uint32_t h2_u32(__half2 v) {
    union { __half2 h; uint32_t u; } c; c.h = v; return c.u;
}
__device__ __forceinline__ uint32_t smem_u32(const void* p) {
    uint32_t a;
    asm("{ .reg .u64 t; cvta.to.shared.u64 t, %1; cvt.u32.u64 %0, t; }" : "=r"(a) : "l"(p));
    return a;
}
__device__ __forceinline__ void cp16(uint32_t dst, const void* src) {
    asm volatile("cp.async.cg.shared.global [%0], [%1], 16;" :: "r"(dst), "l"(src) : "memory");
}
#define CP_COMMIT() asm volatile("cp.async.commit_group;" ::: "memory")
#define CP_WAIT0()  asm volatile("cp.async.wait_group 0;" ::: "memory")
#define CP_WAIT1()  asm volatile("cp.async.wait_group 1;" ::: "memory")

__device__ __forceinline__ void ldm_x4(uint32_t a, uint32_t* r) {
    asm volatile("ldmatrix.sync.aligned.m8n8.x4.shared.b16 {%0,%1,%2,%3}, [%4];"
                 : "=r"(r[0]), "=r"(r[1]), "=r"(r[2]), "=r"(r[3]) : "r"(a));
}
__device__ __forceinline__ void ldm_x4_t(uint32_t a, uint32_t* r) {
    asm volatile("ldmatrix.sync.aligned.m8n8.x4.trans.shared.b16 {%0,%1,%2,%3}, [%4];"
                 : "=r"(r[0]), "=r"(r[1]), "=r"(r[2]), "=r"(r[3]) : "r"(a));
}
__device__ __forceinline__ void mma16816(float* c, const uint32_t* a, const uint32_t* b) {
    asm volatile("mma.sync.aligned.m16n8k16.row.col.f32.f16.f16.f32 "
                 "{%0,%1,%2,%3}, {%4,%5,%6,%7}, {%8,%9}, {%0,%1,%2,%3};"
                 : "+f"(c[0]), "+f"(c[1]), "+f"(c[2]), "+f"(c[3])
                 : "r"(a[0]), "r"(a[1]), "r"(a[2]), "r"(a[3]), "r"(b[0]), "r"(b[1]));
}
__device__ __forceinline__ void sts32f(uint32_t addr, float v) {
    asm volatile("st.shared.f32 [%0], %1;" :: "r"(addr), "f"(v) : "memory");
}
__device__ __forceinline__ float lds32f(uint32_t addr) {
    float v; asm volatile("ld.shared.f32 %0, [%1];" : "=f"(v) : "r"(addr)); return v;
}
__device__ __forceinline__ float4 lds128f(uint32_t addr) {
    float4 v;
    asm volatile("ld.shared.v4.f32 {%0,%1,%2,%3}, [%4];"
                 : "=f"(v.x), "=f"(v.y), "=f"(v.z), "=f"(v.w) : "r"(addr));
    return v;
}
__device__ __forceinline__ void sts128u(uint32_t addr, uint32_t a, uint32_t b, uint32_t c, uint32_t d) {
    asm volatile("st.shared.v4.b32 [%0], {%1,%2,%3,%4};"
                 :: "r"(addr), "r"(a), "r"(b), "r"(c), "r"(d) : "memory");
}
__device__ __forceinline__ void sts64f(uint32_t addr, float a, float b) {
    asm volatile("st.shared.v2.f32 [%0], {%1,%2};" :: "r"(addr), "f"(a), "f"(b) : "memory");
}

// ---------------------------------------------------------------------------
// prep kernels
// ---------------------------------------------------------------------------
__global__ __launch_bounds__(256)
void wt_kernel(const float* __restrict__ W0, const float* __restrict__ W1,
               const float* __restrict__ W2, const float* __restrict__ W3)
{
    __shared__ float t[32][33];
    const int z = blockIdx.z;
    const float* W = (z == 0) ? W0 : (z == 1) ? W1 : (z == 2) ? W2 : W3;
    __half* O = g_w[z];
    const int n0 = blockIdx.x * 32, k0 = blockIdx.y * 32;
    const int tx = threadIdx.x & 31, ty = threadIdx.x >> 5;
#pragma unroll
    for (int i = 0; i < 4; i++)
        t[ty + i*8][tx] = W[(size_t)(k0 + ty + i*8) * PD + n0 + tx];
    __syncthreads();
#pragma unroll
    for (int i = 0; i < 4; i++) {
        const int n = n0 + ty + i*8;
        O[(size_t)n * PD + k0 + tx] = __float2half_rn(t[tx][ty + i*8]);
    }
}

__device__ __forceinline__ void split_vec(const float* __restrict__ src,
                                          __half* __restrict__ hi,
                                          __half* __restrict__ lo, int i)
{
    const float4 v = ((const float4*)src)[i];
    const __half hx = __float2half_rn(v.x);
    const __half hy = __float2half_rn(v.y);
    const __half hz = __float2half_rn(v.z);
    const __half hw = __float2half_rn(v.w);
    __half2* H = (__half2*)hi;
    __half2* L = (__half2*)lo;
    H[i*2 + 0] = __halves2half2(hx, hy);
    H[i*2 + 1] = __halves2half2(hz, hw);
    L[i*2 + 0] = __halves2half2(__float2half_rn(v.x - __half2float(hx)),
                                __float2half_rn(v.y - __half2float(hy)));
    L[i*2 + 1] = __halves2half2(__float2half_rn(v.z - __half2float(hz)),
                                __float2half_rn(v.w - __half2float(hw)));
}

__global__ __launch_bounds__(256)
void split_qkv_kernel(const float* __restrict__ q, const float* __restrict__ k,
                      const float* __restrict__ v)
{
    const int z = blockIdx.y;
    const float* src = (z == 0) ? q : (z == 1) ? k : v;
    split_vec(src, g_ah[z], g_al[z], blockIdx.x * 256 + threadIdx.x);
}

// ---------------------------------------------------------------------------
// fp16 2-product GEMM: C = (Ah+Al) @ B^T (+bias)
// CTA 128x128, KC=32, 3-stage cp.async; smem/chunk = 24KB (Ah|Al|B)
// out_mode 0: fp32 [m][n] + bias
// out_mode 1: Q split hi/lo to head layout
// out_mode 2: single fp16 to head layout
// ---------------------------------------------------------------------------
#define KCH 32
#define NCHUNK (PD / KCH)
#define VOFF 8192
#define BUFOFF 24576
#define GEMM_DYN (3 * BUFOFF)     // 73728

__device__ __forceinline__ void stage_chunk(
    uint32_t sb, const __half* __restrict__ Ah, const __half* __restrict__ Al,
    const __half* __restrict__ B, int m0, int n0, int kt, int tid)
{
#pragma unroll
    for (int i = 0; i < 2; ++i) {
        const int idx = tid + i * 256;
        const int row = idx >> 2;
        const int seg = idx & 3;
        const uint32_t doff = (uint32_t)(row * 64 + ((seg ^ ((row >> 1) & 3)) * 16));
        const size_t aoff = (size_t)(m0 + row) * PD + kt + seg * 8;
        const size_t boff = (size_t)(n0 + row) * PD + kt + seg * 8;
        cp16(sb + 0*VOFF + doff, Ah + aoff);
        cp16(sb + 1*VOFF + doff, Al + aoff);
        cp16(sb + 2*VOFF + doff, B + boff);
    }
}

__device__ __forceinline__ void gemm_core(
    const __half* __restrict__ Ah, const __half* __restrict__ Al,
    const __half* __restrict__ B, const float* __restrict__ bias,
    float* __restrict__ C, __half* __restrict__ Ch, __half* __restrict__ Cl,
    int out_mode)
{
    extern __shared__ char dsm[];
    const uint32_t sb = smem_u32(dsm);
    const int tid  = threadIdx.x;
    const int wid  = tid >> 5;
    const int lane = tid & 31;
    const int m0 = blockIdx.y * 128;
    const int n0 = blockIdx.x * 128;

    const int wm = (wid & 1) * 64;
    const int wn = (wid >> 1) * 32;

    const int ag   = lane >> 3;
    const int arow = wm + (lane & 7) + 8 * (ag & 1);
    const int aseg = ag >> 1;
    const uint32_t a_off = (uint32_t)(arow * 64 + ((aseg ^ ((arow >> 1) & 3)) * 16));

    const int bsg  = (lane >> 3) & 1;
    const int brow_in = ((lane >> 4) & 1) * 8 + (lane & 7);
    const int brow0 = wn + brow_in;
    const int brow1 = wn + 16 + brow_in;
    const uint32_t b_off0 = (uint32_t)(brow0 * 64 + ((bsg ^ ((brow0 >> 1) & 3)) * 16));
    const uint32_t b_off1 = (uint32_t)(brow1 * 64 + ((bsg ^ ((brow1 >> 1) & 3)) * 16));

    float acc[4][4][4];
#pragma unroll
    for (int mt = 0; mt < 4; mt++)
#pragma unroll
        for (int nt = 0; nt < 4; nt++)
#pragma unroll
            for (int r = 0; r < 4; r++) acc[mt][nt][r] = 0.f;

    stage_chunk(sb + 0*BUFOFF, Ah, Al, B, m0, n0, 0*KCH, tid);
    CP_COMMIT();
    stage_chunk(sb + 1*BUFOFF, Ah, Al, B, m0, n0, 1*KCH, tid);
    CP_COMMIT();

    int bufidx = 0, stageidx = 2;
    for (int c = 0; c < NCHUNK; ++c) {
        if (c + 1 < NCHUNK) { CP_WAIT1(); } else { CP_WAIT0(); }
        __syncthreads();
        if (c + 2 < NCHUNK) {
            stage_chunk(sb + stageidx * BUFOFF, Ah, Al, B, m0, n0, (c + 2) * KCH, tid);
            CP_COMMIT();
            stageidx = (stageidx == 2) ? 0 : stageidx + 1;
        }
        const uint32_t buf = sb + bufidx * BUFOFF;
        bufidx = (bufidx == 2) ? 0 : bufidx + 1;

#pragma unroll
        for (int ks = 0; ks < 2; ++ks) {
            const uint32_t kx = ks * 32;
            uint32_t ah[4][4], al[4][4], bh[4][2];
#pragma unroll
            for (int mt = 0; mt < 4; mt++)
                ldm_x4(buf + 0*VOFF + mt*1024 + (a_off ^ kx), ah[mt]);
            ldm_x4(buf + 2*VOFF + (b_off0 ^ kx), &bh[0][0]);
            ldm_x4(buf + 2*VOFF + (b_off1 ^ kx), &bh[2][0]);
#pragma unroll
            for (int mt = 0; mt < 4; mt++)
#pragma unroll
                for (int nt = 0; nt < 4; nt++)
                    mma16816(acc[mt][nt], ah[mt], bh[nt]);
#pragma unroll
            for (int mt = 0; mt < 4; mt++)
                ldm_x4(buf + 1*VOFF + mt*1024 + (a_off ^ kx), al[mt]);
#pragma unroll
            for (int mt = 0; mt < 4; mt++)
#pragma unroll
                for (int nt = 0; nt < 4; nt++)
                    mma16816(acc[mt][nt], al[mt], bh[nt]);
        }
        __syncthreads();
    }

    const int g4 = lane >> 2;
    const int t4 = lane & 3;
#pragma unroll
    for (int nt = 0; nt < 4; nt++) {
        const int col = n0 + wn + nt * 8 + t4 * 2;
        const float2 bv = *(const float2*)(bias + col);
#pragma unroll
        for (int mt = 0; mt < 4; mt++) {
            const int row = m0 + wm + mt * 16 + g4;
            float2 v0, v1;
            v0.x = acc[mt][nt][0] + bv.x;  v0.y = acc[mt][nt][1] + bv.y;
            v1.x = acc[mt][nt][2] + bv.x;  v1.y = acc[mt][nt][3] + bv.y;
            if (out_mode == 0) {
                *(float2*)(C + (size_t)row * PD + col)       = v0;
                *(float2*)(C + (size_t)(row + 8) * PD + col) = v1;
            } else {
                const int b = row >> 8, h = col >> 6, dk = col & 63;
                const int nn = row & 255;
                const size_t base = (((size_t)(b * PH + h)) * PN + nn) * PDK + dk;
                const __half h0x = __float2half_rn(v0.x);
                const __half h0y = __float2half_rn(v0.y);
                const __half h1x = __float2half_rn(v1.x);
                const __half h1y = __float2half_rn(v1.y);
                *(__half2*)(Ch + base)          = __halves2half2(h0x, h0y);
                *(__half2*)(Ch + base + 8*PDK)  = __halves2half2(h1x, h1y);
                if (out_mode == 1) {
                    *(__half2*)(Cl + base) =
                        __halves2half2(__float2half_rn(v0.x - __half2float(h0x)),
                                       __float2half_rn(v0.y - __half2float(h0y)));
                    *(__half2*)(Cl + base + 8*PDK) =
                        __halves2half2(__float2half_rn(v1.x - __half2float(h1x)),
                                       __float2half_rn(v1.y - __half2float(h1y)));
                }
            }
        }
    }
}

__global__ __launch_bounds__(256, 2)
void qkv_mma_kernel(const float* __restrict__ bq, const float* __restrict__ bk,
                    const float* __restrict__ bv)
{
    const int z = blockIdx.z;
    if (z == 0)
        gemm_core(g_ah[0], g_al[0], g_w[0], bq, nullptr, g_q2h, g_q2l, 1);
    else if (z == 1)
        gemm_core(g_ah[1], g_al[1], g_w[1], bk, nullptr, g_k1, nullptr, 2);
    else
        gemm_core(g_ah[2], g_al[2], g_w[2], bv, nullptr, g_v1, nullptr, 2);
}

__global__ __launch_bounds__(256, 2)
void out_mma_kernel(const float* __restrict__ bo, float* __restrict__ out)
{
    gemm_core(g_xh, g_xl, g_w[3], bo, out, nullptr, nullptr, 0);
}

// ---------------------------------------------------------------------------
// pd kernel
// ---------------------------------------------------------------------------
__global__ __launch_bounds__(256)
void pd_kernel(const float* __restrict__ adj, const float* __restrict__ dist,
               const int* __restrict__ mask)
{
    const int bi = blockIdx.x;
    const int b  = bi >> 8;
    const int j  = threadIdx.x;
    const int lane = j & 31, warp = j >> 5;

    const float a  = adj[(size_t)bi*PN + j];
    const int   mj = mask[(b << 8) + j];
    const float nd = mj ? -dist[(size_t)bi*PN + j] : -CUDART_INF_F;

    __shared__ float red[8];

    float v = a;
#pragma unroll
    for (int o = 16; o > 0; o >>= 1) v += __shfl_xor_sync(0xffffffffu, v, o);
    if (lane == 0) red[warp] = v;
    __syncthreads();
    float asum = red[0];
#pragma unroll
    for (int w = 1; w < 8; w++) asum += red[w];
    __syncthreads();

    v = nd;
#pragma unroll
    for (int o = 16; o > 0; o >>= 1) v = fmaxf(v, __shfl_xor_sync(0xffffffffu, v, o));
    if (lane == 0) red[warp] = v;
    __syncthreads();
    float m = red[0];
#pragma unroll
    for (int w = 1; w < 8; w++) m = fmaxf(m, red[w]);
    __syncthreads();

    const float e = mj ? expf(nd - m) : 0.f;
    v = e;
#pragma unroll
    for (int o = 16; o > 0; o >>= 1) v += __shfl_xor_sync(0xffffffffu, v, o);
    if (lane == 0) red[warp] = v;
    __syncthreads();
    float esum = red[0];
#pragma unroll
    for (int w = 1; w < 8; w++) esum += red[w];

    g_pd[(size_t)bi*PN + j] = LAM_ADJ_C * a / (asum + 1e-6f) + LAM_DIST * (e / esum);
}

// ---------------------------------------------------------------------------
// mma attention: one CTA per (b, h, 128-q half)
// smem: Qh|Ql (32KB) | K -> V (32KB) | S/P (130KB) | pen (1KB)  ~195KB
// S row (fp32, 1024B) overwritten in place by P row (fp16, 512B)
// ---------------------------------------------------------------------------
#define SQ_OFF   0
#define SK_OFF   32768
#define SS_OFF   65536
#define SROWB    1040
#define SPEN_OFF (SS_OFF + 128*SROWB)      // 198656
#define ATT_DYN  (SPEN_OFF + 1024)         // 199680

__global__ __launch_bounds__(256, 1)
void attn_mma_kernel(const int* __restrict__ mask)
{
    extern __shared__ char dsm[];
    const uint32_t sb = smem_u32(dsm);
    const int tid = threadIdx.x;
    const int wid = tid >> 5, lane = tid & 31;
    const int b = blockIdx.z, h = blockIdx.y;
    const int q0 = blockIdx.x * 128;
    const int bh = b * PH + h;

    const size_t head = (size_t)bh * PN * PDK;
    const __half* Qh = g_q2h + head + (size_t)q0 * PDK;
    const __half* Ql = g_q2l + head + (size_t)q0 * PDK;

    // stage Q (128x64 hi/lo) and K (256x64), 128B swizzled rows
    for (int i = tid; i < 1024; i += 256) {
        const int row = i >> 3, s = i & 7;
        const uint32_t d = (uint32_t)(row * 128 + ((s ^ (row & 7)) << 4));
        cp16(sb + SQ_OFF + d,         Qh + row * 64 + s * 8);
        cp16(sb + SQ_OFF + 16384 + d, Ql + row * 64 + s * 8);
    }
    for (int i = tid; i < 2048; i += 256) {
        const int row = i >> 3, s = i & 7;
        const uint32_t d = (uint32_t)(row * 128 + ((s ^ (row & 7)) << 4));
        cp16(sb + SK_OFF + d, g_k1 + head + row * 64 + s * 8);
    }
    CP_COMMIT();
    sts32f(sb + SPEN_OFF + tid * 4, mask[(b << 8) + tid] ? 0.f : -1e12f);
    CP_WAIT0();
    __syncthreads();

    // ---------------- phase A: S = (Qh+Ql) @ K^T ----------------
    {
        const int wm = (wid & 1) * 64;
        const int wn = (wid >> 1) * 32;
        const int ag = lane >> 3;
        const int arow = wm + (lane & 7) + 8 * (ag & 1);
        const int aseg0 = ag >> 1;
        const int bsg = (lane >> 3) & 1;
        const int brow_in = ((lane >> 4) & 1) * 8 + (lane & 7);

        for (int nh = 0; nh < 2; ++nh) {
            float acc[4][4][4];
#pragma unroll
            for (int mt = 0; mt < 4; mt++)
#pragma unroll
                for (int nt = 0; nt < 4; nt++)
#pragma unroll
                    for (int r = 0; r < 4; r++) acc[mt][nt][r] = 0.f;

#pragma unroll
            for (int k = 0; k < 4; ++k) {
                uint32_t ahf[4][4], alf[4][4], bhf[4][2];
#pragma unroll
                for (int mt = 0; mt < 4; mt++) {
                    const int r = arow + mt * 16;
                    const uint32_t ad = sb + SQ_OFF + (uint32_t)(r * 128
                                      + (((2*k + aseg0) ^ (r & 7)) << 4));
                    ldm_x4(ad, ahf[mt]);
                    ldm_x4(ad + 16384, alf[mt]);
                }
#pragma unroll
                for (int p = 0; p < 2; p++) {
                    const int r = nh * 128 + wn + p * 16 + brow_in;
                    const uint32_t bd = sb + SK_OFF + (uint32_t)(r * 128
                                      + (((2*k + bsg) ^ (r & 7)) << 4));
                    ldm_x4(bd, &bhf[p*2][0]);
                }
#pragma unroll
                for (int mt = 0; mt < 4; mt++)
#pragma unroll
                    for (int nt = 0; nt < 4; nt++) {
                        mma16816(acc[mt][nt], ahf[mt], bhf[nt]);
                        mma16816(acc[mt][nt], alf[mt], bhf[nt]);
                    }
            }
            const int g4 = lane >> 2, t4 = lane & 3;
#pragma unroll
            for (int mt = 0; mt < 4; mt++) {
                const int row = wm + mt * 16 + g4;
#pragma unroll
                for (int nt = 0; nt < 4; nt++) {
                    const int col = nh * 128 + wn + nt * 8 + t4 * 2;
                    sts64f(sb + SS_OFF + (uint32_t)(row * SROWB + col * 4),
                           acc[mt][nt][0], acc[mt][nt][1]);
                    sts64f(sb + SS_OFF + (uint32_t)((row + 8) * SROWB + col * 4),
                           acc[mt][nt][2], acc[mt][nt][3]);
                }
            }
        }
    }
    __syncthreads();

    // ---------------- phase B: V staging + softmax + pd -> P fp16 (in place)
    for (int i = tid; i < 2048; i += 256) {
        const int row = i >> 3, s = i & 7;
        const uint32_t d = (uint32_t)(row * 128 + ((s ^ (row & 7)) << 4));
        cp16(sb + SK_OFF + d, g_v1 + head + row * 64 + s * 8);
    }
    CP_COMMIT();

    {
        float pen[8];
#pragma unroll
        for (int i = 0; i < 8; i++)
            pen[i] = lds32f(sb + SPEN_OFF + (lane * 8 + i) * 4);
        const float* pdbase = g_pd + ((size_t)b * PN + q0) * PN;

        for (int r = wid * 16; r < wid * 16 + 16; ++r) {
            const uint32_t rb = sb + SS_OFF + (uint32_t)(r * SROWB) + lane * 32;
            float4 s0 = lds128f(rb);
            float4 s1 = lds128f(rb + 16);
            float v[8];
            v[0] = s0.x*0.125f + pen[0]; v[1] = s0.y*0.125f + pen[1];
            v[2] = s0.z*0.125f + pen[2]; v[3] = s0.w*0.125f + pen[3];
            v[4] = s1.x*0.125f + pen[4]; v[5] = s1.y*0.125f + pen[5];
            v[6] = s1.z*0.125f + pen[6]; v[7] = s1.w*0.125f + pen[7];
            float m = v[0];
#pragma unroll
            for (int i = 1; i < 8; i++) m = fmaxf(m, v[i]);
#pragma unroll
            for (int o = 16; o > 0; o >>= 1) m = fmaxf(m, __shfl_xor_sync(0xffffffffu, m, o));
            float e[8], sum = 0.f;
#pragma unroll
            for (int i = 0; i < 8; i++) { e[i] = __expf(v[i] - m); sum += e[i]; }
#pragma unroll
            for (int o = 16; o > 0; o >>= 1) sum += __shfl_xor_sync(0xffffffffu, sum, o);
            const float scale = LAM_ATT / sum;
            const float4 p0 = *(const float4*)(pdbase + (size_t)r * PN + lane * 8);
            const float4 p1 = *(const float4*)(pdbase + (size_t)r * PN + lane * 8 + 4);
            float p[8];
            p[0] = e[0]*scale + p0.x; p[1] = e[1]*scale + p0.y;
            p[2] = e[2]*scale + p0.z; p[3] = e[3]*scale + p0.w;
            p[4] = e[4]*scale + p1.x; p[5] = e[5]*scale + p1.y;
            p[6] = e[6]*scale + p1.z; p[7] = e[7]*scale + p1.w;
            uint32_t hi[4];
#pragma unroll
            for (int i = 0; i < 4; i++)
                hi[i] = h2_u32(__halves2half2(__float2half_rn(p[2*i]),
                                              __float2half_rn(p[2*i+1])));
            const uint32_t pb = sb + SS_OFF + (uint32_t)(r * SROWB) + lane * 16;
            sts128u(pb, hi[0], hi[1], hi[2], hi[3]);
        }
    }
    CP_WAIT0();
    __syncthreads();

    // ---------------- phase C: O = P @ V ----------------
    {
        const int wm = (wid & 1) * 64;
        const int wn = (wid >> 1) * 16;
        const int ag = lane >> 3;
        const int arow = wm + (lane & 7) + 8 * (ag & 1);
        const int aseg0 = ag >> 1;

        // V ldmatrix.x4.trans lane mapping: g = lane>>3
        // key half = g&1, dk 8-group = g>>1
        const int vg = lane >> 3;
        const int vkey_in = (vg & 1) * 8 + (lane & 7);
        const int vds_in  = vg >> 1;

        float acc[4][2][4];
#pragma unroll
        for (int mt = 0; mt < 4; mt++)
#pragma unroll
            for (int nt = 0; nt < 2; nt++)
#pragma unroll
                for (int r = 0; r < 4; r++) acc[mt][nt][r] = 0.f;

        for (int k = 0; k < 16; ++k) {
            uint32_t ph[4][4], vh[4];
#pragma unroll
            for (int mt = 0; mt < 4; mt++) {
                const int r = arow + mt * 16;
                ldm_x4(sb + SS_OFF + (uint32_t)(r * SROWB + (2*k + aseg0) * 16), ph[mt]);
            }
            {
                const int key = k * 16 + vkey_in;
                const int ds  = (wn >> 3) + vds_in;
                ldm_x4_t(sb + SK_OFF + (uint32_t)(key * 128 + ((ds ^ (key & 7)) << 4)),
                         vh);
            }
#pragma unroll
            for (int mt = 0; mt < 4; mt++)
#pragma unroll
                for (int nt = 0; nt < 2; nt++)
                    mma16816(acc[mt][nt], ph[mt], &vh[nt*2]);
        }

        // epilogue: split fp32 O -> g_xh/g_xl at [b*256+q][h*64+dk]
        const int g4 = lane >> 2, t4 = lane & 3;
#pragma unroll
        for (int mt = 0; mt < 4; mt++) {
#pragma unroll
            for (int nt = 0; nt < 2; nt++) {
                const int colg = h * PDK + wn + nt * 8 + t4 * 2;
#pragma unroll
                for (int half = 0; half < 2; half++) {
                    const int mg = b * PN + q0 + wm + mt * 16 + g4 + half * 8;
                    const float vx = acc[mt][nt][half*2 + 0];
                    const float vy = acc[mt][nt][half*2 + 1];
                    const __half hx = __float2half_rn(vx);
                    const __half hy = __float2half_rn(vy);
                    *(__half2*)(g_xh + (size_t)mg * PD + colg) = __halves2half2(hx, hy);
                    *(__half2*)(g_xl + (size_t)mg * PD + colg) =
                        __halves2half2(__float2half_rn(vx - __half2float(hx)),
                                       __float2half_rn(vy - __half2float(hy)));
                }
            }
        }
    }
}

// ---------------------------------------------------------------------------
extern "C" void kernel_launch(void* const* d_in, const int* in_sizes, int n_in,
                              void* d_out, int out_size)
{
    const float* query = (const float*)d_in[0];
    const float* key   = (const float*)d_in[1];
    const float* value = (const float*)d_in[2];
    const float* adj   = (const float*)d_in[3];
    const float* dist  = (const float*)d_in[4];
    const int*   mask  = (const int*)d_in[6];
    const float* Wq = (const float*)d_in[7];
    const float* bq = (const float*)d_in[8];
    const float* Wk = (const float*)d_in[9];
    const float* bk = (const float*)d_in[10];
    const float* Wv = (const float*)d_in[11];
    const float* bv = (const float*)d_in[12];
    const float* Wo = (const float*)d_in[13];
    const float* bo = (const float*)d_in[14];
    float* out = (float*)d_out;

    static bool attr_set = false;
    if (!attr_set) {
        cudaFuncSetAttribute(qkv_mma_kernel, cudaFuncAttributeMaxDynamicSharedMemorySize, GEMM_DYN);
        cudaFuncSetAttribute(out_mma_kernel, cudaFuncAttributeMaxDynamicSharedMemorySize, GEMM_DYN);
        cudaFuncSetAttribute(attn_mma_kernel, cudaFuncAttributeMaxDynamicSharedMemorySize, ATT_DYN);
        attr_set = true;
    }

    wt_kernel<<<dim3(32, 32, 4), 256>>>(Wq, Wk, Wv, Wo);
    split_qkv_kernel<<<dim3(GM*PD/4/256, 3), 256>>>(query, key, value);

    qkv_mma_kernel<<<dim3(PD/128, GM/128, 3), 256, GEMM_DYN>>>(bq, bk, bv);

    pd_kernel<<<PB*PN, 256>>>(adj, dist, mask);

    attn_mma_kernel<<<dim3(2, PH, PB), 256, ATT_DYN>>>(mask);

    out_mma_kernel<<<dim3(PD/128, GM/128, 1), 256, GEMM_DYN>>>(bo, out);
}

// round 15
// speedup vs baseline: 2.1684x; 1.4597x over previous
#include <cuda_runtime.h>
#include <cuda_fp16.h>
#include <math_constants.h>
#include <cstdint>

// ---------------- problem constants ----------------
#define PB 16
#define PN 256
#define PD 1024
#define PH 16
#define PDK 64
#define GM (PB*PN)   // 4096

#define LAM_ATT 0.33f
#define LAM_DIST 0.33f
__device__ __constant__ float LAM_ADJ_C = (float)(1.0 - 0.33 - 0.33);

// ---------------- device scratch ----------------
__device__ float g_pd[PB*PN*PN];

__device__ __half g_w[4][PD*PD];      // weights transposed [n][k]
__device__ __half g_a[3][GM*PD];      // activations q/k/v inputs
// projected tensors, head layout [b][h][n][dk]
__device__ __half g_q1[GM*PD];
__device__ __half g_k1[GM*PD];
__device__ __half g_v1[GM*PD];
// attention output [m][d]
__device__ __half g_x1[GM*PD];

// ---------------- helpers ----------------
__device__ __forceinline__ uint32_t h2_u32(__half2 v) {
    union { __half2 h; uint32_t u; } c; c.h = v; return c.u;
}
__device__ __forceinline__ uint32_t smem_u32(const void* p) {
    uint32_t a;
    asm("{ .reg .u64 t; cvta.to.shared.u64 t, %1; cvt.u32.u64 %0, t; }" : "=r"(a) : "l"(p));
    return a;
}
__device__ __forceinline__ void cp16(uint32_t dst, const void* src) {
    asm volatile("cp.async.cg.shared.global [%0], [%1], 16;" :: "r"(dst), "l"(src) : "memory");
}
#define CP_COMMIT() asm volatile("cp.async.commit_group;" ::: "memory")
#define CP_WAIT0()  asm volatile("cp.async.wait_group 0;" ::: "memory")
#define CP_WAIT1()  asm volatile("cp.async.wait_group 1;" ::: "memory")

__device__ __forceinline__ void ldm_x4(uint32_t a, uint32_t* r) {
    asm volatile("ldmatrix.sync.aligned.m8n8.x4.shared.b16 {%0,%1,%2,%3}, [%4];"
                 : "=r"(r[0]), "=r"(r[1]), "=r"(r[2]), "=r"(r[3]) : "r"(a));
}
__device__ __forceinline__ void ldm_x4_t(uint32_t a, uint32_t* r) {
    asm volatile("ldmatrix.sync.aligned.m8n8.x4.trans.shared.b16 {%0,%1,%2,%3}, [%4];"
                 : "=r"(r[0]), "=r"(r[1]), "=r"(r[2]), "=r"(r[3]) : "r"(a));
}
__device__ __forceinline__ void mma16816(float* c, const uint32_t* a, const uint32_t* b) {
    asm volatile("mma.sync.aligned.m16n8k16.row.col.f32.f16.f16.f32 "
                 "{%0,%1,%2,%3}, {%4,%5,%6,%7}, {%8,%9}, {%0,%1,%2,%3};"
                 : "+f"(c[0]), "+f"(c[1]), "+f"(c[2]), "+f"(c[3])
                 : "r"(a[0]), "r"(a[1]), "r"(a[2]), "r"(a[3]), "r"(b[0]), "r"(b[1]));
}
__device__ __forceinline__ void sts32f(uint32_t addr, float v) {
    asm volatile("st.shared.f32 [%0], %1;" :: "r"(addr), "f"(v) : "memory");
}
__device__ __forceinline__ float lds32f(uint32_t addr) {
    float v; asm volatile("ld.shared.f32 %0, [%1];" : "=f"(v) : "r"(addr)); return v;
}
__device__ __forceinline__ float4 lds128f(uint32_t addr) {
    float4 v;
    asm volatile("ld.shared.v4.f32 {%0,%1,%2,%3}, [%4];"
                 : "=f"(v.x), "=f"(v.y), "=f"(v.z), "=f"(v.w) : "r"(addr));
    return v;
}
__device__ __forceinline__ void sts128u(uint32_t addr, uint32_t a, uint32_t b, uint32_t c, uint32_t d) {
    asm volatile("st.shared.v4.b32 [%0], {%1,%2,%3,%4};"
                 :: "r"(addr), "r"(a), "r"(b), "r"(c), "r"(d) : "memory");
}
__device__ __forceinline__ void sts64f(uint32_t addr, float a, float b) {
    asm volatile("st.shared.v2.f32 [%0], {%1,%2};" :: "r"(addr), "f"(a), "f"(b) : "memory");
}

// ---------------------------------------------------------------------------
// prep kernels
// ---------------------------------------------------------------------------
__global__ __launch_bounds__(256)
void wt_kernel(const float* __restrict__ W0, const float* __restrict__ W1,
               const float* __restrict__ W2, const float* __restrict__ W3)
{
    __shared__ float t[32][33];
    const int z = blockIdx.z;
    const float* W = (z == 0) ? W0 : (z == 1) ? W1 : (z == 2) ? W2 : W3;
    __half* O = g_w[z];
    const int n0 = blockIdx.x * 32, k0 = blockIdx.y * 32;
    const int tx = threadIdx.x & 31, ty = threadIdx.x >> 5;
#pragma unroll
    for (int i = 0; i < 4; i++)
        t[ty + i*8][tx] = W[(size_t)(k0 + ty + i*8) * PD + n0 + tx];
    __syncthreads();
#pragma unroll
    for (int i = 0; i < 4; i++) {
        const int n = n0 + ty + i*8;
        O[(size_t)n * PD + k0 + tx] = __float2half_rn(t[tx][ty + i*8]);
    }
}

__global__ __launch_bounds__(256)
void cvt_qkv_kernel(const float* __restrict__ q, const float* __restrict__ k,
                    const float* __restrict__ v)
{
    const int z = blockIdx.y;
    const float* src = (z == 0) ? q : (z == 1) ? k : v;
    const int i = blockIdx.x * 256 + threadIdx.x;
    const float4 x = ((const float4*)src)[i];
    __half2* H = (__half2*)g_a[z];
    H[i*2 + 0] = __halves2half2(__float2half_rn(x.x), __float2half_rn(x.y));
    H[i*2 + 1] = __halves2half2(__float2half_rn(x.z), __float2half_rn(x.w));
}

// ---------------------------------------------------------------------------
// fp16 single-product GEMM: C = A @ B^T (+bias)
// CTA 128x128, KC=32, 3-stage cp.async; smem/chunk = 16KB (A|B)
// out_mode 0: fp32 [m][n] + bias
// out_mode 1: single fp16 to head layout
// ---------------------------------------------------------------------------
#define KCH 32
#define NCHUNK (PD / KCH)
#define VOFF 8192
#define BUFOFF 16384
#define GEMM_DYN (3 * BUFOFF)     // 49152

__device__ __forceinline__ void stage_chunk(
    uint32_t sb, const __half* __restrict__ A, const __half* __restrict__ B,
    int m0, int n0, int kt, int tid)
{
#pragma unroll
    for (int i = 0; i < 2; ++i) {
        const int idx = tid + i * 256;
        const int row = idx >> 2;
        const int seg = idx & 3;
        const uint32_t doff = (uint32_t)(row * 64 + ((seg ^ ((row >> 1) & 3)) * 16));
        cp16(sb + 0*VOFF + doff, A + (size_t)(m0 + row) * PD + kt + seg * 8);
        cp16(sb + 1*VOFF + doff, B + (size_t)(n0 + row) * PD + kt + seg * 8);
    }
}

__device__ __forceinline__ void gemm_core(
    const __half* __restrict__ A, const __half* __restrict__ B,
    const float* __restrict__ bias, float* __restrict__ C,
    __half* __restrict__ Ch, int out_mode)
{
    extern __shared__ char dsm[];
    const uint32_t sb = smem_u32(dsm);
    const int tid  = threadIdx.x;
    const int wid  = tid >> 5;
    const int lane = tid & 31;
    const int m0 = blockIdx.y * 128;
    const int n0 = blockIdx.x * 128;

    const int wm = (wid & 1) * 64;
    const int wn = (wid >> 1) * 32;

    const int ag   = lane >> 3;
    const int arow = wm + (lane & 7) + 8 * (ag & 1);
    const int aseg = ag >> 1;
    const uint32_t a_off = (uint32_t)(arow * 64 + ((aseg ^ ((arow >> 1) & 3)) * 16));

    const int bsg  = (lane >> 3) & 1;
    const int brow_in = ((lane >> 4) & 1) * 8 + (lane & 7);
    const int brow0 = wn + brow_in;
    const int brow1 = wn + 16 + brow_in;
    const uint32_t b_off0 = (uint32_t)(brow0 * 64 + ((bsg ^ ((brow0 >> 1) & 3)) * 16));
    const uint32_t b_off1 = (uint32_t)(brow1 * 64 + ((bsg ^ ((brow1 >> 1) & 3)) * 16));

    float acc[4][4][4];
#pragma unroll
    for (int mt = 0; mt < 4; mt++)
#pragma unroll
        for (int nt = 0; nt < 4; nt++)
#pragma unroll
            for (int r = 0; r < 4; r++) acc[mt][nt][r] = 0.f;

    stage_chunk(sb + 0*BUFOFF, A, B, m0, n0, 0*KCH, tid);
    CP_COMMIT();
    stage_chunk(sb + 1*BUFOFF, A, B, m0, n0, 1*KCH, tid);
    CP_COMMIT();

    int bufidx = 0, stageidx = 2;
    for (int c = 0; c < NCHUNK; ++c) {
        if (c + 1 < NCHUNK) { CP_WAIT1(); } else { CP_WAIT0(); }
        __syncthreads();
        if (c + 2 < NCHUNK) {
            stage_chunk(sb + stageidx * BUFOFF, A, B, m0, n0, (c + 2) * KCH, tid);
            CP_COMMIT();
            stageidx = (stageidx == 2) ? 0 : stageidx + 1;
        }
        const uint32_t buf = sb + bufidx * BUFOFF;
        bufidx = (bufidx == 2) ? 0 : bufidx + 1;

#pragma unroll
        for (int ks = 0; ks < 2; ++ks) {
            const uint32_t kx = ks * 32;
            uint32_t ah[4][4], bh[4][2];
#pragma unroll
            for (int mt = 0; mt < 4; mt++)
                ldm_x4(buf + 0*VOFF + mt*1024 + (a_off ^ kx), ah[mt]);
            ldm_x4(buf + 1*VOFF + (b_off0 ^ kx), &bh[0][0]);
            ldm_x4(buf + 1*VOFF + (b_off1 ^ kx), &bh[2][0]);
#pragma unroll
            for (int mt = 0; mt < 4; mt++)
#pragma unroll
                for (int nt = 0; nt < 4; nt++)
                    mma16816(acc[mt][nt], ah[mt], bh[nt]);
        }
        __syncthreads();
    }

    const int g4 = lane >> 2;
    const int t4 = lane & 3;
#pragma unroll
    for (int nt = 0; nt < 4; nt++) {
        const int col = n0 + wn + nt * 8 + t4 * 2;
        const float2 bv = *(const float2*)(bias + col);
#pragma unroll
        for (int mt = 0; mt < 4; mt++) {
            const int row = m0 + wm + mt * 16 + g4;
            float2 v0, v1;
            v0.x = acc[mt][nt][0] + bv.x;  v0.y = acc[mt][nt][1] + bv.y;
            v1.x = acc[mt][nt][2] + bv.x;  v1.y = acc[mt][nt][3] + bv.y;
            if (out_mode == 0) {
                *(float2*)(C + (size_t)row * PD + col)       = v0;
                *(float2*)(C + (size_t)(row + 8) * PD + col) = v1;
            } else {
                const int b = row >> 8, h = col >> 6, dk = col & 63;
                const int nn = row & 255;
                const size_t base = (((size_t)(b * PH + h)) * PN + nn) * PDK + dk;
                *(__half2*)(Ch + base) =
                    __halves2half2(__float2half_rn(v0.x), __float2half_rn(v0.y));
                *(__half2*)(Ch + base + 8*PDK) =
                    __halves2half2(__float2half_rn(v1.x), __float2half_rn(v1.y));
            }
        }
    }
}

__global__ __launch_bounds__(256, 2)
void qkv_mma_kernel(const float* __restrict__ bq, const float* __restrict__ bk,
                    const float* __restrict__ bv)
{
    const int z = blockIdx.z;
    __half* Ch = (z == 0) ? g_q1 : (z == 1) ? g_k1 : g_v1;
    gemm_core(g_a[z], g_w[z], (z == 0) ? bq : (z == 1) ? bk : bv,
              nullptr, Ch, 1);
}

__global__ __launch_bounds__(256, 2)
void out_mma_kernel(const float* __restrict__ bo, float* __restrict__ out)
{
    gemm_core(g_x1, g_w[3], bo, out, nullptr, 0);
}

// ---------------------------------------------------------------------------
// pd kernel
// ---------------------------------------------------------------------------
__global__ __launch_bounds__(256)
void pd_kernel(const float* __restrict__ adj, const float* __restrict__ dist,
               const int* __restrict__ mask)
{
    const int bi = blockIdx.x;
    const int b  = bi >> 8;
    const int j  = threadIdx.x;
    const int lane = j & 31, warp = j >> 5;

    const float a  = adj[(size_t)bi*PN + j];
    const int   mj = mask[(b << 8) + j];
    const float nd = mj ? -dist[(size_t)bi*PN + j] : -CUDART_INF_F;

    __shared__ float red[8];

    float v = a;
#pragma unroll
    for (int o = 16; o > 0; o >>= 1) v += __shfl_xor_sync(0xffffffffu, v, o);
    if (lane == 0) red[warp] = v;
    __syncthreads();
    float asum = red[0];
#pragma unroll
    for (int w = 1; w < 8; w++) asum += red[w];
    __syncthreads();

    v = nd;
#pragma unroll
    for (int o = 16; o > 0; o >>= 1) v = fmaxf(v, __shfl_xor_sync(0xffffffffu, v, o));
    if (lane == 0) red[warp] = v;
    __syncthreads();
    float m = red[0];
#pragma unroll
    for (int w = 1; w < 8; w++) m = fmaxf(m, red[w]);
    __syncthreads();

    const float e = mj ? expf(nd - m) : 0.f;
    v = e;
#pragma unroll
    for (int o = 16; o > 0; o >>= 1) v += __shfl_xor_sync(0xffffffffu, v, o);
    if (lane == 0) red[warp] = v;
    __syncthreads();
    float esum = red[0];
#pragma unroll
    for (int w = 1; w < 8; w++) esum += red[w];

    g_pd[(size_t)bi*PN + j] = LAM_ADJ_C * a / (asum + 1e-6f) + LAM_DIST * (e / esum);
}

// ---------------------------------------------------------------------------
// mma attention: one CTA per (b, h, 128-q half)
// smem: Q (16KB) | K -> V (32KB) | S/P (130KB) | pen (1KB)  ~180KB
// S row (fp32, 1024B) overwritten in place by P row (fp16, 512B)
// ---------------------------------------------------------------------------
#define SQ_OFF   0
#define SK_OFF   16384
#define SS_OFF   49152
#define SROWB    1040
#define SPEN_OFF (SS_OFF + 128*SROWB)      // 182272
#define ATT_DYN  (SPEN_OFF + 1024)         // 183296

__global__ __launch_bounds__(256, 1)
void attn_mma_kernel(const int* __restrict__ mask)
{
    extern __shared__ char dsm[];
    const uint32_t sb = smem_u32(dsm);
    const int tid = threadIdx.x;
    const int wid = tid >> 5, lane = tid & 31;
    const int b = blockIdx.z, h = blockIdx.y;
    const int q0 = blockIdx.x * 128;
    const int bh = b * PH + h;

    const size_t head = (size_t)bh * PN * PDK;
    const __half* Qg = g_q1 + head + (size_t)q0 * PDK;

    // stage Q (128x64) and K (256x64), 128B swizzled rows
    for (int i = tid; i < 1024; i += 256) {
        const int row = i >> 3, s = i & 7;
        const uint32_t d = (uint32_t)(row * 128 + ((s ^ (row & 7)) << 4));
        cp16(sb + SQ_OFF + d, Qg + row * 64 + s * 8);
    }
    for (int i = tid; i < 2048; i += 256) {
        const int row = i >> 3, s = i & 7;
        const uint32_t d = (uint32_t)(row * 128 + ((s ^ (row & 7)) << 4));
        cp16(sb + SK_OFF + d, g_k1 + head + row * 64 + s * 8);
    }
    CP_COMMIT();
    sts32f(sb + SPEN_OFF + tid * 4, mask[(b << 8) + tid] ? 0.f : -1e12f);
    CP_WAIT0();
    __syncthreads();

    // ---------------- phase A: S = Q @ K^T ----------------
    {
        const int wm = (wid & 1) * 64;
        const int wn = (wid >> 1) * 32;
        const int ag = lane >> 3;
        const int arow = wm + (lane & 7) + 8 * (ag & 1);
        const int aseg0 = ag >> 1;
        const int bsg = (lane >> 3) & 1;
        const int brow_in = ((lane >> 4) & 1) * 8 + (lane & 7);

        for (int nh = 0; nh < 2; ++nh) {
            float acc[4][4][4];
#pragma unroll
            for (int mt = 0; mt < 4; mt++)
#pragma unroll
                for (int nt = 0; nt < 4; nt++)
#pragma unroll
                    for (int r = 0; r < 4; r++) acc[mt][nt][r] = 0.f;

#pragma unroll
            for (int k = 0; k < 4; ++k) {
                uint32_t ahf[4][4], bhf[4][2];
#pragma unroll
                for (int mt = 0; mt < 4; mt++) {
                    const int r = arow + mt * 16;
                    ldm_x4(sb + SQ_OFF + (uint32_t)(r * 128
                           + (((2*k + aseg0) ^ (r & 7)) << 4)), ahf[mt]);
                }
#pragma unroll
                for (int p = 0; p < 2; p++) {
                    const int r = nh * 128 + wn + p * 16 + brow_in;
                    ldm_x4(sb + SK_OFF + (uint32_t)(r * 128
                           + (((2*k + bsg) ^ (r & 7)) << 4)), &bhf[p*2][0]);
                }
#pragma unroll
                for (int mt = 0; mt < 4; mt++)
#pragma unroll
                    for (int nt = 0; nt < 4; nt++)
                        mma16816(acc[mt][nt], ahf[mt], bhf[nt]);
            }
            const int g4 = lane >> 2, t4 = lane & 3;
#pragma unroll
            for (int mt = 0; mt < 4; mt++) {
                const int row = wm + mt * 16 + g4;
#pragma unroll
                for (int nt = 0; nt < 4; nt++) {
                    const int col = nh * 128 + wn + nt * 8 + t4 * 2;
                    sts64f(sb + SS_OFF + (uint32_t)(row * SROWB + col * 4),
                           acc[mt][nt][0], acc[mt][nt][1]);
                    sts64f(sb + SS_OFF + (uint32_t)((row + 8) * SROWB + col * 4),
                           acc[mt][nt][2], acc[mt][nt][3]);
                }
            }
        }
    }
    __syncthreads();

    // ---------------- phase B: V staging + softmax + pd -> P fp16 (in place)
    for (int i = tid; i < 2048; i += 256) {
        const int row = i >> 3, s = i & 7;
        const uint32_t d = (uint32_t)(row * 128 + ((s ^ (row & 7)) << 4));
        cp16(sb + SK_OFF + d, g_v1 + head + row * 64 + s * 8);
    }
    CP_COMMIT();

    {
        float pen[8];
#pragma unroll
        for (int i = 0; i < 8; i++)
            pen[i] = lds32f(sb + SPEN_OFF + (lane * 8 + i) * 4);
        const float* pdbase = g_pd + ((size_t)b * PN + q0) * PN;

        for (int r = wid * 16; r < wid * 16 + 16; ++r) {
            const uint32_t rb = sb + SS_OFF + (uint32_t)(r * SROWB) + lane * 32;
            float4 s0 = lds128f(rb);
            float4 s1 = lds128f(rb + 16);
            float v[8];
            v[0] = s0.x*0.125f + pen[0]; v[1] = s0.y*0.125f + pen[1];
            v[2] = s0.z*0.125f + pen[2]; v[3] = s0.w*0.125f + pen[3];
            v[4] = s1.x*0.125f + pen[4]; v[5] = s1.y*0.125f + pen[5];
            v[6] = s1.z*0.125f + pen[6]; v[7] = s1.w*0.125f + pen[7];
            float m = v[0];
#pragma unroll
            for (int i = 1; i < 8; i++) m = fmaxf(m, v[i]);
#pragma unroll
            for (int o = 16; o > 0; o >>= 1) m = fmaxf(m, __shfl_xor_sync(0xffffffffu, m, o));
            float e[8], sum = 0.f;
#pragma unroll
            for (int i = 0; i < 8; i++) { e[i] = __expf(v[i] - m); sum += e[i]; }
#pragma unroll
            for (int o = 16; o > 0; o >>= 1) sum += __shfl_xor_sync(0xffffffffu, sum, o);
            const float scale = LAM_ATT / sum;
            const float4 p0 = *(const float4*)(pdbase + (size_t)r * PN + lane * 8);
            const float4 p1 = *(const float4*)(pdbase + (size_t)r * PN + lane * 8 + 4);
            float p[8];
            p[0] = e[0]*scale + p0.x; p[1] = e[1]*scale + p0.y;
            p[2] = e[2]*scale + p0.z; p[3] = e[3]*scale + p0.w;
            p[4] = e[4]*scale + p1.x; p[5] = e[5]*scale + p1.y;
            p[6] = e[6]*scale + p1.z; p[7] = e[7]*scale + p1.w;
            uint32_t hi[4];
#pragma unroll
            for (int i = 0; i < 4; i++)
                hi[i] = h2_u32(__halves2half2(__float2half_rn(p[2*i]),
                                              __float2half_rn(p[2*i+1])));
            const uint32_t pb = sb + SS_OFF + (uint32_t)(r * SROWB) + lane * 16;
            sts128u(pb, hi[0], hi[1], hi[2], hi[3]);
        }
    }
    CP_WAIT0();
    __syncthreads();

    // ---------------- phase C: O = P @ V ----------------
    {
        const int wm = (wid & 1) * 64;
        const int wn = (wid >> 1) * 16;
        const int ag = lane >> 3;
        const int arow = wm + (lane & 7) + 8 * (ag & 1);
        const int aseg0 = ag >> 1;

        const int vg = lane >> 3;
        const int vkey_in = (vg & 1) * 8 + (lane & 7);
        const int vds_in  = vg >> 1;

        float acc[4][2][4];
#pragma unroll
        for (int mt = 0; mt < 4; mt++)
#pragma unroll
            for (int nt = 0; nt < 2; nt++)
#pragma unroll
                for (int r = 0; r < 4; r++) acc[mt][nt][r] = 0.f;

        for (int k = 0; k < 16; ++k) {
            uint32_t ph[4][4], vh[4];
#pragma unroll
            for (int mt = 0; mt < 4; mt++) {
                const int r = arow + mt * 16;
                ldm_x4(sb + SS_OFF + (uint32_t)(r * SROWB + (2*k + aseg0) * 16), ph[mt]);
            }
            {
                const int key = k * 16 + vkey_in;
                const int ds  = (wn >> 3) + vds_in;
                ldm_x4_t(sb + SK_OFF + (uint32_t)(key * 128 + ((ds ^ (key & 7)) << 4)),
                         vh);
            }
#pragma unroll
            for (int mt = 0; mt < 4; mt++)
#pragma unroll
                for (int nt = 0; nt < 2; nt++)
                    mma16816(acc[mt][nt], ph[mt], &vh[nt*2]);
        }

        // epilogue: O -> g_x1 (single fp16) at [b*256+q][h*64+dk]
        const int g4 = lane >> 2, t4 = lane & 3;
#pragma unroll
        for (int mt = 0; mt < 4; mt++) {
#pragma unroll
            for (int nt = 0; nt < 2; nt++) {
                const int colg = h * PDK + wn + nt * 8 + t4 * 2;
#pragma unroll
                for (int half = 0; half < 2; half++) {
                    const int mg = b * PN + q0 + wm + mt * 16 + g4 + half * 8;
                    *(__half2*)(g_x1 + (size_t)mg * PD + colg) =
                        __halves2half2(__float2half_rn(acc[mt][nt][half*2 + 0]),
                                       __float2half_rn(acc[mt][nt][half*2 + 1]));
                }
            }
        }
    }
}

// ---------------------------------------------------------------------------
extern "C" void kernel_launch(void* const* d_in, const int* in_sizes, int n_in,
                              void* d_out, int out_size)
{
    const float* query = (const float*)d_in[0];
    const float* key   = (const float*)d_in[1];
    const float* value = (const float*)d_in[2];
    const float* adj   = (const float*)d_in[3];
    const float* dist  = (const float*)d_in[4];
    const int*   mask  = (const int*)d_in[6];
    const float* Wq = (const float*)d_in[7];
    const float* bq = (const float*)d_in[8];
    const float* Wk = (const float*)d_in[9];
    const float* bk = (const float*)d_in[10];
    const float* Wv = (const float*)d_in[11];
    const float* bv = (const float*)d_in[12];
    const float* Wo = (const float*)d_in[13];
    const float* bo = (const float*)d_in[14];
    float* out = (float*)d_out;

    static bool attr_set = false;
    if (!attr_set) {
        cudaFuncSetAttribute(qkv_mma_kernel, cudaFuncAttributeMaxDynamicSharedMemorySize, GEMM_DYN);
        cudaFuncSetAttribute(out_mma_kernel, cudaFuncAttributeMaxDynamicSharedMemorySize, GEMM_DYN);
        cudaFuncSetAttribute(attn_mma_kernel, cudaFuncAttributeMaxDynamicSharedMemorySize, ATT_DYN);
        attr_set = true;
    }

    wt_kernel<<<dim3(32, 32, 4), 256>>>(Wq, Wk, Wv, Wo);
    cvt_qkv_kernel<<<dim3(GM*PD/4/256, 3), 256>>>(query, key, value);

    qkv_mma_kernel<<<dim3(PD/128, GM/128, 3), 256, GEMM_DYN>>>(bq, bk, bv);

    pd_kernel<<<PB*PN, 256>>>(adj, dist, mask);

    attn_mma_kernel<<<dim3(2, PH, PB), 256, ATT_DYN>>>(mask);

    out_mma_kernel<<<dim3(PD/128, GM/128, 1), 256, GEMM_DYN>>>(bo, out);
}

// round 17
// speedup vs baseline: 2.4415x; 1.1259x over previous
#include <cuda_runtime.h>
#include <cuda_fp16.h>
#include <math_constants.h>
#include <cstdint>

// ---------------- problem constants ----------------
#define PB 16
#define PN 256
#define PD 1024
#define PH 16
#define PDK 64
#define GM (PB*PN)   // 4096

#define LAM_ATT 0.33f
#define LAM_DIST 0.33f
__device__ __constant__ float LAM_ADJ_C = (float)(1.0 - 0.33 - 0.33);

// ---------------- device scratch ----------------
__device__ float g_pd[PB*PN*PN];

__device__ __half g_w[4][PD*PD];      // weights transposed [n][k]
__device__ __half g_a[3][GM*PD];      // activations q/k/v inputs
// projected tensors, head layout [b][h][n][dk]
__device__ __half g_q1[GM*PD];
__device__ __half g_k1[GM*PD];
__device__ __half g_v1[GM*PD];
// attention output [m][d]
__device__ __half g_x1[GM*PD];

// ---------------- helpers ----------------
__device__ __forceinline__ uint32_t h2_u32(__half2 v) {
    union { __half2 h; uint32_t u; } c; c.h = v; return c.u;
}
__device__ __forceinline__ uint32_t smem_u32(const void* p) {
    uint32_t a;
    asm("{ .reg .u64 t; cvta.to.shared.u64 t, %1; cvt.u32.u64 %0, t; }" : "=r"(a) : "l"(p));
    return a;
}
__device__ __forceinline__ void cp16(uint32_t dst, const void* src) {
    asm volatile("cp.async.cg.shared.global [%0], [%1], 16;" :: "r"(dst), "l"(src) : "memory");
}
#define CP_COMMIT() asm volatile("cp.async.commit_group;" ::: "memory")
#define CP_WAIT0()  asm volatile("cp.async.wait_group 0;" ::: "memory")
#define CP_WAIT1()  asm volatile("cp.async.wait_group 1;" ::: "memory")

__device__ __forceinline__ void ldm_x4(uint32_t a, uint32_t* r) {
    asm volatile("ldmatrix.sync.aligned.m8n8.x4.shared.b16 {%0,%1,%2,%3}, [%4];"
                 : "=r"(r[0]), "=r"(r[1]), "=r"(r[2]), "=r"(r[3]) : "r"(a));
}
__device__ __forceinline__ void ldm_x4_t(uint32_t a, uint32_t* r) {
    asm volatile("ldmatrix.sync.aligned.m8n8.x4.trans.shared.b16 {%0,%1,%2,%3}, [%4];"
                 : "=r"(r[0]), "=r"(r[1]), "=r"(r[2]), "=r"(r[3]) : "r"(a));
}
__device__ __forceinline__ void mma16816(float* c, const uint32_t* a, const uint32_t* b) {
    asm volatile("mma.sync.aligned.m16n8k16.row.col.f32.f16.f16.f32 "
                 "{%0,%1,%2,%3}, {%4,%5,%6,%7}, {%8,%9}, {%0,%1,%2,%3};"
                 : "+f"(c[0]), "+f"(c[1]), "+f"(c[2]), "+f"(c[3])
                 : "r"(a[0]), "r"(a[1]), "r"(a[2]), "r"(a[3]), "r"(b[0]), "r"(b[1]));
}
__device__ __forceinline__ float lds32f(uint32_t addr) {
    float v; asm volatile("ld.shared.f32 %0, [%1];" : "=f"(v) : "r"(addr)); return v;
}
__device__ __forceinline__ float4 lds128f(uint32_t addr) {
    float4 v;
    asm volatile("ld.shared.v4.f32 {%0,%1,%2,%3}, [%4];"
                 : "=f"(v.x), "=f"(v.y), "=f"(v.z), "=f"(v.w) : "r"(addr));
    return v;
}
__device__ __forceinline__ void sts128u(uint32_t addr, uint32_t a, uint32_t b, uint32_t c, uint32_t d) {
    asm volatile("st.shared.v4.b32 [%0], {%1,%2,%3,%4};"
                 :: "r"(addr), "r"(a), "r"(b), "r"(c), "r"(d) : "memory");
}
__device__ __forceinline__ void sts64f(uint32_t addr, float a, float b) {
    asm volatile("st.shared.v2.f32 [%0], {%1,%2};" :: "r"(addr), "f"(a), "f"(b) : "memory");
}

// ---------------------------------------------------------------------------
// merged prep kernel: grid (4096, 7)
//   y in [0,4): weight transpose+round — ONLY blockIdx.x < 1024 (32x32 tiles)
//   y in [4,7): activation fp32->fp16 convert (z = y-4), all 4096 blocks
// ---------------------------------------------------------------------------
__global__ __launch_bounds__(256)
void prep_kernel(const float* __restrict__ W0, const float* __restrict__ W1,
                 const float* __restrict__ W2, const float* __restrict__ W3,
                 const float* __restrict__ q, const float* __restrict__ k,
                 const float* __restrict__ v)
{
    __shared__ float t[32][33];
    if (blockIdx.y < 4) {
        if (blockIdx.x >= 1024) return;          // weight role has 1024 tiles only
        const int z = blockIdx.y;
        const float* W = (z == 0) ? W0 : (z == 1) ? W1 : (z == 2) ? W2 : W3;
        __half* O = g_w[z];
        const int n0 = (blockIdx.x & 31) * 32;
        const int k0 = (blockIdx.x >> 5) * 32;   // < 1024 now
        const int tx = threadIdx.x & 31, ty = threadIdx.x >> 5;
#pragma unroll
        for (int i = 0; i < 4; i++)
            t[ty + i*8][tx] = W[(size_t)(k0 + ty + i*8) * PD + n0 + tx];
        __syncthreads();
#pragma unroll
        for (int i = 0; i < 4; i++) {
            const int n = n0 + ty + i*8;
            O[(size_t)n * PD + k0 + tx] = __float2half_rn(t[tx][ty + i*8]);
        }
    } else {
        const int z = blockIdx.y - 4;
        const float* src = (z == 0) ? q : (z == 1) ? k : v;
        const int i = blockIdx.x * 256 + threadIdx.x;
        const float4 x = ((const float4*)src)[i];
        __half2* H = (__half2*)g_a[z];
        H[i*2 + 0] = __halves2half2(__float2half_rn(x.x), __float2half_rn(x.y));
        H[i*2 + 1] = __halves2half2(__float2half_rn(x.z), __float2half_rn(x.w));
    }
}

// ---------------------------------------------------------------------------
// fp16 single-product GEMM: C = A @ B^T (+bias)
// CTA 128x128, KC=32, 3-stage cp.async; smem/chunk = 16KB (A|B)
// ---------------------------------------------------------------------------
#define KCH 32
#define NCHUNK (PD / KCH)
#define VOFF 8192
#define BUFOFF 16384
#define GEMM_DYN (3 * BUFOFF)     // 49152

__device__ __forceinline__ void stage_chunk(
    uint32_t sb, const __half* __restrict__ A, const __half* __restrict__ B,
    int m0, int n0, int kt, int tid)
{
#pragma unroll
    for (int i = 0; i < 2; ++i) {
        const int idx = tid + i * 256;
        const int row = idx >> 2;
        const int seg = idx & 3;
        const uint32_t doff = (uint32_t)(row * 64 + ((seg ^ ((row >> 1) & 3)) * 16));
        cp16(sb + 0*VOFF + doff, A + (size_t)(m0 + row) * PD + kt + seg * 8);
        cp16(sb + 1*VOFF + doff, B + (size_t)(n0 + row) * PD + kt + seg * 8);
    }
}

__device__ __forceinline__ void gemm_core(
    const __half* __restrict__ A, const __half* __restrict__ B,
    const float* __restrict__ bias, float* __restrict__ C,
    __half* __restrict__ Ch, int out_mode)
{
    extern __shared__ char dsm[];
    const uint32_t sb = smem_u32(dsm);
    const int tid  = threadIdx.x;
    const int wid  = tid >> 5;
    const int lane = tid & 31;
    const int m0 = blockIdx.y * 128;
    const int n0 = blockIdx.x * 128;

    const int wm = (wid & 1) * 64;
    const int wn = (wid >> 1) * 32;

    const int ag   = lane >> 3;
    const int arow = wm + (lane & 7) + 8 * (ag & 1);
    const int aseg = ag >> 1;
    const uint32_t a_off = (uint32_t)(arow * 64 + ((aseg ^ ((arow >> 1) & 3)) * 16));

    const int bsg  = (lane >> 3) & 1;
    const int brow_in = ((lane >> 4) & 1) * 8 + (lane & 7);
    const int brow0 = wn + brow_in;
    const int brow1 = wn + 16 + brow_in;
    const uint32_t b_off0 = (uint32_t)(brow0 * 64 + ((bsg ^ ((brow0 >> 1) & 3)) * 16));
    const uint32_t b_off1 = (uint32_t)(brow1 * 64 + ((bsg ^ ((brow1 >> 1) & 3)) * 16));

    float acc[4][4][4];
#pragma unroll
    for (int mt = 0; mt < 4; mt++)
#pragma unroll
        for (int nt = 0; nt < 4; nt++)
#pragma unroll
            for (int r = 0; r < 4; r++) acc[mt][nt][r] = 0.f;

    stage_chunk(sb + 0*BUFOFF, A, B, m0, n0, 0*KCH, tid);
    CP_COMMIT();
    stage_chunk(sb + 1*BUFOFF, A, B, m0, n0, 1*KCH, tid);
    CP_COMMIT();

    int bufidx = 0, stageidx = 2;
    for (int c = 0; c < NCHUNK; ++c) {
        if (c + 1 < NCHUNK) { CP_WAIT1(); } else { CP_WAIT0(); }
        __syncthreads();
        if (c + 2 < NCHUNK) {
            stage_chunk(sb + stageidx * BUFOFF, A, B, m0, n0, (c + 2) * KCH, tid);
            CP_COMMIT();
            stageidx = (stageidx == 2) ? 0 : stageidx + 1;
        }
        const uint32_t buf = sb + bufidx * BUFOFF;
        bufidx = (bufidx == 2) ? 0 : bufidx + 1;

#pragma unroll
        for (int ks = 0; ks < 2; ++ks) {
            const uint32_t kx = ks * 32;
            uint32_t ah[4][4], bh[4][2];
#pragma unroll
            for (int mt = 0; mt < 4; mt++)
                ldm_x4(buf + 0*VOFF + mt*1024 + (a_off ^ kx), ah[mt]);
            ldm_x4(buf + 1*VOFF + (b_off0 ^ kx), &bh[0][0]);
            ldm_x4(buf + 1*VOFF + (b_off1 ^ kx), &bh[2][0]);
#pragma unroll
            for (int mt = 0; mt < 4; mt++)
#pragma unroll
                for (int nt = 0; nt < 4; nt++)
                    mma16816(acc[mt][nt], ah[mt], bh[nt]);
        }
        __syncthreads();
    }

    const int g4 = lane >> 2;
    const int t4 = lane & 3;
#pragma unroll
    for (int nt = 0; nt < 4; nt++) {
        const int col = n0 + wn + nt * 8 + t4 * 2;
        const float2 bv = *(const float2*)(bias + col);
#pragma unroll
        for (int mt = 0; mt < 4; mt++) {
            const int row = m0 + wm + mt * 16 + g4;
            float2 v0, v1;
            v0.x = acc[mt][nt][0] + bv.x;  v0.y = acc[mt][nt][1] + bv.y;
            v1.x = acc[mt][nt][2] + bv.x;  v1.y = acc[mt][nt][3] + bv.y;
            if (out_mode == 0) {
                *(float2*)(C + (size_t)row * PD + col)       = v0;
                *(float2*)(C + (size_t)(row + 8) * PD + col) = v1;
            } else {
                const int b = row >> 8, h = col >> 6, dk = col & 63;
                const int nn = row & 255;
                const size_t base = (((size_t)(b * PH + h)) * PN + nn) * PDK + dk;
                *(__half2*)(Ch + base) =
                    __halves2half2(__float2half_rn(v0.x), __float2half_rn(v0.y));
                *(__half2*)(Ch + base + 8*PDK) =
                    __halves2half2(__float2half_rn(v1.x), __float2half_rn(v1.y));
            }
        }
    }
}

// ---------------------------------------------------------------------------
// combined qkv GEMM + pd kernel: grid (8, 32, 4)
//   z in [0,3): projection GEMMs (head-split fp16 out)
//   z == 3:    pd map, warp-per-row (256 blocks x 16 rows)
// ---------------------------------------------------------------------------
__global__ __launch_bounds__(256, 2)
void qkv_pd_kernel(const float* __restrict__ bq, const float* __restrict__ bk,
                   const float* __restrict__ bv,
                   const float* __restrict__ adj, const float* __restrict__ dist,
                   const int* __restrict__ mask)
{
    const int z = blockIdx.z;
    if (z < 3) {
        __half* Ch = (z == 0) ? g_q1 : (z == 1) ? g_k1 : g_v1;
        gemm_core(g_a[z], g_w[z], (z == 0) ? bq : (z == 1) ? bk : bv,
                  nullptr, Ch, 1);
        return;
    }
    // pd: LAM_ADJ*adj_norm + LAM_DIST*softmax(-dist, mask)
    const int wid = threadIdx.x >> 5, lane = threadIdx.x & 31;
    const int base = (blockIdx.y * 8 + blockIdx.x) * 16 + wid * 2;
#pragma unroll
    for (int rr = 0; rr < 2; ++rr) {
        const int bi = base + rr;          // 0..4095
        const int b  = bi >> 8;
        float av[8], nv[8], e[8];
        int mj[8];
#pragma unroll
        for (int t = 0; t < 8; ++t) {
            const int j = lane + 32 * t;
            av[t] = adj[(size_t)bi * PN + j];
            mj[t] = mask[(b << 8) + j];
            nv[t] = mj[t] ? -dist[(size_t)bi * PN + j] : -CUDART_INF_F;
        }
        float asum = 0.f, m = -CUDART_INF_F;
#pragma unroll
        for (int t = 0; t < 8; ++t) { asum += av[t]; m = fmaxf(m, nv[t]); }
#pragma unroll
        for (int o = 16; o > 0; o >>= 1) {
            asum += __shfl_xor_sync(0xffffffffu, asum, o);
            m = fmaxf(m, __shfl_xor_sync(0xffffffffu, m, o));
        }
        float esum = 0.f;
#pragma unroll
        for (int t = 0; t < 8; ++t) { e[t] = mj[t] ? expf(nv[t] - m) : 0.f; esum += e[t]; }
#pragma unroll
        for (int o = 16; o > 0; o >>= 1) esum += __shfl_xor_sync(0xffffffffu, esum, o);
        const float ia = LAM_ADJ_C / (asum + 1e-6f);
        const float ie = LAM_DIST / esum;
#pragma unroll
        for (int t = 0; t < 8; ++t)
            g_pd[(size_t)bi * PN + lane + 32 * t] = av[t] * ia + e[t] * ie;
    }
}

__global__ __launch_bounds__(256, 2)
void out_mma_kernel(const float* __restrict__ bo, float* __restrict__ out)
{
    gemm_core(g_x1, g_w[3], bo, out, nullptr, 0);
}

// ---------------------------------------------------------------------------
// mma attention: one CTA per (b, h, 64-q quarter); 2 CTAs/SM
// smem: Q (8KB) | K -> V (32KB) | S/P (65KB, stride 1040B)  = 105KB
// S row (fp32, 1024B) overwritten in place by P row (fp16, 512B)
// ---------------------------------------------------------------------------
#define SQ_OFF   0
#define SK_OFF   8192
#define SS_OFF   40960
#define SROWB    1040
#define ATT_DYN  (SS_OFF + 64*SROWB)       // 107520

__global__ __launch_bounds__(256, 2)
void attn_mma_kernel(const int* __restrict__ mask)
{
    extern __shared__ char dsm[];
    const uint32_t sb = smem_u32(dsm);
    const int tid = threadIdx.x;
    const int wid = tid >> 5, lane = tid & 31;
    const int b = blockIdx.z, h = blockIdx.y;
    const int q0 = blockIdx.x * 64;
    const int bh = b * PH + h;

    const size_t head = (size_t)bh * PN * PDK;
    const __half* Qg = g_q1 + head + (size_t)q0 * PDK;

    // stage Q (64x64) and K (256x64), 128B swizzled rows
    for (int i = tid; i < 512; i += 256) {
        const int row = i >> 3, s = i & 7;
        const uint32_t d = (uint32_t)(row * 128 + ((s ^ (row & 7)) << 4));
        cp16(sb + SQ_OFF + d, Qg + row * 64 + s * 8);
    }
    for (int i = tid; i < 2048; i += 256) {
        const int row = i >> 3, s = i & 7;
        const uint32_t d = (uint32_t)(row * 128 + ((s ^ (row & 7)) << 4));
        cp16(sb + SK_OFF + d, g_k1 + head + row * 64 + s * 8);
    }
    CP_COMMIT();
    CP_WAIT0();
    __syncthreads();

    // ---------------- phase A: S = Q @ K^T  (64 x 256) ----------------
    {
        const int wm = (wid & 1) * 32;
        const int wn = (wid >> 1) * 32;
        const int ag = lane >> 3;
        const int arow = wm + (lane & 7) + 8 * (ag & 1);
        const int aseg0 = ag >> 1;
        const int bsg = (lane >> 3) & 1;
        const int brow_in = ((lane >> 4) & 1) * 8 + (lane & 7);

        for (int nh = 0; nh < 2; ++nh) {
            float acc[2][4][4];
#pragma unroll
            for (int mt = 0; mt < 2; mt++)
#pragma unroll
                for (int nt = 0; nt < 4; nt++)
#pragma unroll
                    for (int r = 0; r < 4; r++) acc[mt][nt][r] = 0.f;

#pragma unroll
            for (int k = 0; k < 4; ++k) {
                uint32_t ahf[2][4], bhf[4][2];
#pragma unroll
                for (int mt = 0; mt < 2; mt++) {
                    const int r = arow + mt * 16;
                    ldm_x4(sb + SQ_OFF + (uint32_t)(r * 128
                           + (((2*k + aseg0) ^ (r & 7)) << 4)), ahf[mt]);
                }
#pragma unroll
                for (int p = 0; p < 2; p++) {
                    const int r = nh * 128 + wn + p * 16 + brow_in;
                    ldm_x4(sb + SK_OFF + (uint32_t)(r * 128
                           + (((2*k + bsg) ^ (r & 7)) << 4)), &bhf[p*2][0]);
                }
#pragma unroll
                for (int mt = 0; mt < 2; mt++)
#pragma unroll
                    for (int nt = 0; nt < 4; nt++)
                        mma16816(acc[mt][nt], ahf[mt], bhf[nt]);
            }
            const int g4 = lane >> 2, t4 = lane & 3;
#pragma unroll
            for (int mt = 0; mt < 2; mt++) {
                const int row = wm + mt * 16 + g4;
#pragma unroll
                for (int nt = 0; nt < 4; nt++) {
                    const int col = nh * 128 + wn + nt * 8 + t4 * 2;
                    sts64f(sb + SS_OFF + (uint32_t)(row * SROWB + col * 4),
                           acc[mt][nt][0], acc[mt][nt][1]);
                    sts64f(sb + SS_OFF + (uint32_t)((row + 8) * SROWB + col * 4),
                           acc[mt][nt][2], acc[mt][nt][3]);
                }
            }
        }
    }
    __syncthreads();

    // ---------------- phase B: V staging + softmax + pd -> P fp16 (in place)
    for (int i = tid; i < 2048; i += 256) {
        const int row = i >> 3, s = i & 7;
        const uint32_t d = (uint32_t)(row * 128 + ((s ^ (row & 7)) << 4));
        cp16(sb + SK_OFF + d, g_v1 + head + row * 64 + s * 8);
    }
    CP_COMMIT();

    {
        float pen[8];
#pragma unroll
        for (int i = 0; i < 8; i++)
            pen[i] = mask[(b << 8) + lane * 8 + i] ? 0.f : -1e12f;
        const float* pdbase = g_pd + ((size_t)b * PN + q0) * PN;

        for (int r = wid * 8; r < wid * 8 + 8; ++r) {
            const uint32_t rb = sb + SS_OFF + (uint32_t)(r * SROWB) + lane * 32;
            float4 s0 = lds128f(rb);
            float4 s1 = lds128f(rb + 16);
            float v[8];
            v[0] = s0.x*0.125f + pen[0]; v[1] = s0.y*0.125f + pen[1];
            v[2] = s0.z*0.125f + pen[2]; v[3] = s0.w*0.125f + pen[3];
            v[4] = s1.x*0.125f + pen[4]; v[5] = s1.y*0.125f + pen[5];
            v[6] = s1.z*0.125f + pen[6]; v[7] = s1.w*0.125f + pen[7];
            float m = v[0];
#pragma unroll
            for (int i = 1; i < 8; i++) m = fmaxf(m, v[i]);
#pragma unroll
            for (int o = 16; o > 0; o >>= 1) m = fmaxf(m, __shfl_xor_sync(0xffffffffu, m, o));
            float e[8], sum = 0.f;
#pragma unroll
            for (int i = 0; i < 8; i++) { e[i] = __expf(v[i] - m); sum += e[i]; }
#pragma unroll
            for (int o = 16; o > 0; o >>= 1) sum += __shfl_xor_sync(0xffffffffu, sum, o);
            const float scale = LAM_ATT / sum;
            const float4 p0 = *(const float4*)(pdbase + (size_t)r * PN + lane * 8);
            const float4 p1 = *(const float4*)(pdbase + (size_t)r * PN + lane * 8 + 4);
            float p[8];
            p[0] = e[0]*scale + p0.x; p[1] = e[1]*scale + p0.y;
            p[2] = e[2]*scale + p0.z; p[3] = e[3]*scale + p0.w;
            p[4] = e[4]*scale + p1.x; p[5] = e[5]*scale + p1.y;
            p[6] = e[6]*scale + p1.z; p[7] = e[7]*scale + p1.w;
            uint32_t hi[4];
#pragma unroll
            for (int i = 0; i < 4; i++)
                hi[i] = h2_u32(__halves2half2(__float2half_rn(p[2*i]),
                                              __float2half_rn(p[2*i+1])));
            const uint32_t pb = sb + SS_OFF + (uint32_t)(r * SROWB) + lane * 16;
            sts128u(pb, hi[0], hi[1], hi[2], hi[3]);
        }
    }
    CP_WAIT0();
    __syncthreads();

    // ---------------- phase C: O = P @ V  (64 x 64) ----------------
    {
        const int wm = (wid & 1) * 32;
        const int wn = (wid >> 1) * 16;
        const int ag = lane >> 3;
        const int arow = wm + (lane & 7) + 8 * (ag & 1);
        const int aseg0 = ag >> 1;

        const int vg = lane >> 3;
        const int vkey_in = (vg & 1) * 8 + (lane & 7);
        const int vds_in  = vg >> 1;

        float acc[2][2][4];
#pragma unroll
        for (int mt = 0; mt < 2; mt++)
#pragma unroll
            for (int nt = 0; nt < 2; nt++)
#pragma unroll
                for (int r = 0; r < 4; r++) acc[mt][nt][r] = 0.f;

        for (int k = 0; k < 16; ++k) {
            uint32_t ph[2][4], vh[4];
#pragma unroll
            for (int mt = 0; mt < 2; mt++) {
                const int r = arow + mt * 16;
                ldm_x4(sb + SS_OFF + (uint32_t)(r * SROWB + (2*k + aseg0) * 16), ph[mt]);
            }
            {
                const int key = k * 16 + vkey_in;
                const int ds  = (wn >> 3) + vds_in;
                ldm_x4_t(sb + SK_OFF + (uint32_t)(key * 128 + ((ds ^ (key & 7)) << 4)),
                         vh);
            }
#pragma unroll
            for (int mt = 0; mt < 2; mt++)
#pragma unroll
                for (int nt = 0; nt < 2; nt++)
                    mma16816(acc[mt][nt], ph[mt], &vh[nt*2]);
        }

        // epilogue: O -> g_x1 (single fp16) at [b*256+q][h*64+dk]
        const int g4 = lane >> 2, t4 = lane & 3;
#pragma unroll
        for (int mt = 0; mt < 2; mt++) {
#pragma unroll
            for (int nt = 0; nt < 2; nt++) {
                const int colg = h * PDK + wn + nt * 8 + t4 * 2;
#pragma unroll
                for (int half = 0; half < 2; half++) {
                    const int mg = b * PN + q0 + wm + mt * 16 + g4 + half * 8;
                    *(__half2*)(g_x1 + (size_t)mg * PD + colg) =
                        __halves2half2(__float2half_rn(acc[mt][nt][half*2 + 0]),
                                       __float2half_rn(acc[mt][nt][half*2 + 1]));
                }
            }
        }
    }
}

// ---------------------------------------------------------------------------
extern "C" void kernel_launch(void* const* d_in, const int* in_sizes, int n_in,
                              void* d_out, int out_size)
{
    const float* query = (const float*)d_in[0];
    const float* key   = (const float*)d_in[1];
    const float* value = (const float*)d_in[2];
    const float* adj   = (const float*)d_in[3];
    const float* dist  = (const float*)d_in[4];
    const int*   mask  = (const int*)d_in[6];
    const float* Wq = (const float*)d_in[7];
    const float* bq = (const float*)d_in[8];
    const float* Wk = (const float*)d_in[9];
    const float* bk = (const float*)d_in[10];
    const float* Wv = (const float*)d_in[11];
    const float* bv = (const float*)d_in[12];
    const float* Wo = (const float*)d_in[13];
    const float* bo = (const float*)d_in[14];
    float* out = (float*)d_out;

    static bool attr_set = false;
    if (!attr_set) {
        cudaFuncSetAttribute(qkv_pd_kernel, cudaFuncAttributeMaxDynamicSharedMemorySize, GEMM_DYN);
        cudaFuncSetAttribute(out_mma_kernel, cudaFuncAttributeMaxDynamicSharedMemorySize, GEMM_DYN);
        cudaFuncSetAttribute(attn_mma_kernel, cudaFuncAttributeMaxDynamicSharedMemorySize, ATT_DYN);
        attr_set = true;
    }

    // 1) weights transpose+round + activation convert (one launch)
    prep_kernel<<<dim3(4096, 7), 256>>>(Wq, Wk, Wv, Wo, query, key, value);

    // 2) QKV projections + pd map (one launch; pd hides in the GEMM wave)
    qkv_pd_kernel<<<dim3(PD/128, GM/128, 4), 256, GEMM_DYN>>>(
        bq, bk, bv, adj, dist, mask);

    // 3) fused attention (2 CTAs/SM)
    attn_mma_kernel<<<dim3(4, PH, PB), 256, ATT_DYN>>>(mask);

    // 4) output projection
    out_mma_kernel<<<dim3(PD/128, GM/128, 1), 256, GEMM_DYN>>>(bo, out);
}